// round 13
// baseline (speedup 1.0000x reference)
#include <cuda_runtime.h>
#include <cuda_bf16.h>
#include <cstdint>
#include <cstddef>

#define D_MODEL 1024
#define NHEAD   16
#define DK      64
#define BATCH   2
#define SEQ     2048
#define M_TOT   (BATCH * SEQ)                 // 4096
#define NXE     ((size_t)M_TOT * D_MODEL)     // 4M elems
#define NWE     ((size_t)D_MODEL * D_MODEL)   // 1M elems
#define LOG2E   1.4426950408889634f
#define EXPN1   0.36787944117144233f          // e^-1 (masked-score weight)

// Scratch (allocation-free: __device__ globals)
__device__ __nv_bfloat16 g_INh[3 * NXE];   // split q,k,v inputs (hi)
__device__ __nv_bfloat16 g_INl[3 * NXE];   // (lo)
__device__ __nv_bfloat16 g_Wh[4 * NWE];    // split wq,wk,wv,wo (hi)
__device__ __nv_bfloat16 g_Wl[4 * NWE];    // (lo)
__device__ __nv_bfloat16 g_Ph[3 * NXE];    // projected Q,K,V (hi)
__device__ __nv_bfloat16 g_Pl[3 * NXE];    // (lo)
__device__ __nv_bfloat16 g_Ch[NXE];        // attention context (hi)
__device__ __nv_bfloat16 g_Cl[NXE];        // (lo)
__device__ uint64_t      g_maskb[(size_t)SEQ * SEQ / 64];  // bit-packed mask

// ===========================================================================
// Helpers (baseline PTX ISA only — compute_103-safe)
// ===========================================================================
__device__ __forceinline__ uint32_t smem_u32(const void* p) {
    uint32_t a;
    asm("{ .reg .u64 t; cvta.to.shared.u64 t, %1; cvt.u32.u64 %0, t; }"
        : "=r"(a) : "l"(p));
    return a;
}

__device__ __forceinline__ float ex2f(float x) {
    float y;
    asm("ex2.approx.f32 %0, %1;" : "=f"(y) : "f"(x));
    return y;
}

#define LDM4(r, addr) \
    asm volatile("ldmatrix.sync.aligned.m8n8.x4.shared.b16 {%0,%1,%2,%3}, [%4];" \
        : "=r"((r)[0]), "=r"((r)[1]), "=r"((r)[2]), "=r"((r)[3]) : "r"(addr))

#define LDM4_T(r, addr) \
    asm volatile("ldmatrix.sync.aligned.m8n8.x4.trans.shared.b16 {%0,%1,%2,%3}, [%4];" \
        : "=r"((r)[0]), "=r"((r)[1]), "=r"((r)[2]), "=r"((r)[3]) : "r"(addr))

#define MMA_BF16(d, a, b0, b1) \
    asm volatile("mma.sync.aligned.m16n8k16.row.col.f32.bf16.bf16.f32 " \
        "{%0,%1,%2,%3}, {%4,%5,%6,%7}, {%8,%9}, {%0,%1,%2,%3};" \
        : "+f"((d)[0]), "+f"((d)[1]), "+f"((d)[2]), "+f"((d)[3]) \
        : "r"((a)[0]), "r"((a)[1]), "r"((a)[2]), "r"((a)[3]), "r"(b0), "r"(b1))

#define CP16(sa, gp) \
    asm volatile("{ .reg .u64 g; cvta.to.global.u64 g, %1; " \
                 "cp.async.cg.shared.global [%0], [g], 16; }" \
        :: "r"((uint32_t)(sa)), "l"(gp) : "memory")
#define CP_COMMIT  asm volatile("cp.async.commit_group;" ::: "memory")
#define CP_WAIT1   asm volatile("cp.async.wait_group 1;" ::: "memory")
#define CP_WAIT0   asm volatile("cp.async.wait_group 0;" ::: "memory")

__device__ __forceinline__ uint32_t pack_bf16(float a, float b) {
    __nv_bfloat162 h = __floats2bfloat162_rn(a, b);
    return *(uint32_t*)&h;
}
// Truncation split: hi = top 16 bits of fp32, lo = exact residual rounded.
__device__ __forceinline__ uint32_t pack2_hi_trunc(float a, float b) {
    return __byte_perm(__float_as_uint(a), __float_as_uint(b), 0x7632);
}
__device__ __forceinline__ uint32_t pack2_lo_trunc(float a, float b) {
    float ah = __uint_as_float(__float_as_uint(a) & 0xFFFF0000u);
    float bh = __uint_as_float(__float_as_uint(b) & 0xFFFF0000u);
    return pack_bf16(a - ah, b - bh);
}
__device__ __forceinline__ void cvt4_split(float4 f, uint2& hi, uint2& lo) {
    hi.x = pack2_hi_trunc(f.x, f.y);  hi.y = pack2_hi_trunc(f.z, f.w);
    lo.x = pack2_lo_trunc(f.x, f.y);  lo.y = pack2_lo_trunc(f.z, f.w);
}

// XOR swizzle: 128B rows, 16B chunks permuted within row (ldmatrix-safe)
__device__ __forceinline__ uint32_t swz(uint32_t row, uint32_t chunk) {
    return (row << 7) + ((chunk ^ (row & 7)) << 4);
}

// ===========================================================================
// Merged pre-pass: splits q,k,v (3 x 4096 blocks), wq..wo (4 x 1024 blocks),
// and bit-packs the mask (512 blocks at the end).
// ===========================================================================
__global__ void split_all_kernel(
    const float* __restrict__ q,  const float* __restrict__ k,
    const float* __restrict__ v,
    const float* __restrict__ w0, const float* __restrict__ w1,
    const float* __restrict__ w2, const float* __restrict__ w3,
    const int*   __restrict__ m)
{
    const int blk = blockIdx.x;
    if (blk >= 16384) {                      // mask bit-pack: 512 blocks
        const size_t tid  = (size_t)(blk - 16384) * 256 + threadIdx.x;
        const size_t base = tid << 5;        // 32 consecutive ints
        uint32_t bits = 0;
#pragma unroll
        for (int i = 0; i < 8; i++) {
            int4 vv = *(const int4*)(m + base + (i << 2));
            bits |= (vv.x ? 1u : 0u) << (4 * i);
            bits |= (vv.y ? 1u : 0u) << (4 * i + 1);
            bits |= (vv.z ? 1u : 0u) << (4 * i + 2);
            bits |= (vv.w ? 1u : 0u) << (4 * i + 3);
        }
        ((uint32_t*)g_maskb)[tid] = bits;
        return;
    }
    const float* src;
    __nv_bfloat16 *dh, *dl;
    size_t i;
    if (blk < 12288) {                       // inputs: 3 x 4096 blocks
        const int z = blk >> 12;
        src = (z == 0) ? q : (z == 1) ? k : v;
        i = ((size_t)(blk & 4095) * 256 + threadIdx.x) << 2;
        dh = g_INh + (size_t)z * NXE;
        dl = g_INl + (size_t)z * NXE;
    } else {                                 // weights: 4 x 1024 blocks
        const int wblk = blk - 12288;
        const int z = wblk >> 10;
        src = (z == 0) ? w0 : (z == 1) ? w1 : (z == 2) ? w2 : w3;
        i = ((size_t)(wblk & 1023) * 256 + threadIdx.x) << 2;
        dh = g_Wh + (size_t)z * NWE;
        dl = g_Wl + (size_t)z * NWE;
    }
    float4 f = *(const float4*)(src + i);
    uint2 hi, lo; cvt4_split(f, hi, lo);
    *(uint2*)(dh + i) = hi;
    *(uint2*)(dl + i) = lo;
}

// ===========================================================================
// GEMM core (pre-split bf16 operands, cp.async 3-stage pipeline)
// CTA tile 128x128, BK=32. smem stage 32K: A(hi|lo packed rows) 16K + B 16K.
// ===========================================================================
#define GSTG      32768
#define GEMM_SMEM (3 * GSTG)   // 98304

__device__ __forceinline__ void gemm_core(
    const __nv_bfloat16* __restrict__ Xh, const __nv_bfloat16* __restrict__ Xl,
    const __nv_bfloat16* __restrict__ Wh, const __nv_bfloat16* __restrict__ Wl,
    uint32_t sb, int m0, int n0, float (&acc)[4][4][4])
{
    const int t    = threadIdx.x;
    const int lane = t & 31;
    const int wid  = t >> 5;
    const int wm   = (wid & 1) << 6;
    const int wn   = (wid >> 1) << 5;

    auto issue = [&](int kt, int s) {
        const uint32_t base = sb + s * GSTG;
        const int k0 = kt << 5;
#pragma unroll
        for (int i = 0; i < 4; i++) {
            const int idx = t + (i << 8);
            const int row = idx >> 3, ch = idx & 7;
            const __nv_bfloat16* px = (ch < 4) ? Xh : Xl;
            const __nv_bfloat16* pw = (ch < 4) ? Wh : Wl;
            const int cc = (ch & 3) << 3;
            const uint32_t so = swz(row, ch);
            CP16(base + so,         px + (size_t)(m0 + row) * D_MODEL + k0 + cc);
            CP16(base + 16384 + so, pw + (size_t)(n0 + row) * D_MODEL + k0 + cc);
        }
    };

    issue(0, 0); CP_COMMIT;
    issue(1, 1); CP_COMMIT;

    for (int kt = 0; kt < 32; kt++) {
        if (kt < 30) { CP_WAIT1; } else { CP_WAIT0; }
        __syncthreads();
        if (kt < 30) { issue(kt + 2, (kt + 2) % 3); CP_COMMIT; }

        const uint32_t abuf = sb + (kt % 3) * GSTG;
        const uint32_t bbuf = abuf + 16384;
#pragma unroll
        for (int ks = 0; ks < 2; ks++) {
            uint32_t bh[4][2], bl[4][2];
#pragma unroll
            for (int p = 0; p < 2; p++) {
                const int nr = wn + (p << 4) + (lane & 7) + ((lane >> 4) << 3);
                const int ch = (ks << 1) + ((lane >> 3) & 1);
                uint32_t qq[4];
                LDM4(qq, bbuf + swz(nr, ch));
                bh[2 * p][0] = qq[0]; bh[2 * p][1] = qq[1];
                bh[2 * p + 1][0] = qq[2]; bh[2 * p + 1][1] = qq[3];
                LDM4(qq, bbuf + swz(nr, ch + 4));
                bl[2 * p][0] = qq[0]; bl[2 * p][1] = qq[1];
                bl[2 * p + 1][0] = qq[2]; bl[2 * p + 1][1] = qq[3];
            }
#pragma unroll
            for (int mi = 0; mi < 4; mi++) {
                const int row = wm + (mi << 4) + (lane & 15);
                const int ch  = (ks << 1) + (lane >> 4);
                uint32_t ah[4], al[4];
                LDM4(ah, abuf + swz(row, ch));
                LDM4(al, abuf + swz(row, ch + 4));
#pragma unroll
                for (int ni = 0; ni < 4; ni++) {
                    MMA_BF16(acc[mi][ni], ah, bh[ni][0], bh[ni][1]);
                    MMA_BF16(acc[mi][ni], ah, bl[ni][0], bl[ni][1]);
                    MMA_BF16(acc[mi][ni], al, bh[ni][0], bh[ni][1]);
                }
            }
        }
    }
}

// ---- batched Q/K/V projections. Q (z==0) pre-scaled by 0.125*log2(e) so
//      attention scores land directly in the exp2 domain. ----
__global__ __launch_bounds__(256, 2) void gemm_qkv_kernel(
    const float* __restrict__ bq, const float* __restrict__ bk,
    const float* __restrict__ bv)
{
    extern __shared__ char sm[];
    const uint32_t sb = smem_u32(sm);
    const int z  = blockIdx.z;
    const int m0 = blockIdx.y << 7;
    const int n0 = blockIdx.x << 7;
    const size_t zo = (size_t)z * NXE;

    float acc[4][4][4] = {};
    gemm_core(g_INh + zo, g_INl + zo,
              g_Wh + (size_t)z * NWE, g_Wl + (size_t)z * NWE,
              sb, m0, n0, acc);

    const float* bias = (z == 0) ? bq : (z == 1) ? bk : bv;
    const float sc = (z == 0) ? (0.125f * LOG2E) : 1.0f;
    __nv_bfloat16* Yh = g_Ph + zo;
    __nv_bfloat16* Yl = g_Pl + zo;

    const int lane = threadIdx.x & 31;
    const int wid  = threadIdx.x >> 5;
    const int wm   = (wid & 1) << 6;
    const int wn   = (wid >> 1) << 5;
    const int lr4  = lane >> 2;
    const int lc2  = (lane & 3) << 1;
#pragma unroll
    for (int mi = 0; mi < 4; mi++) {
        const int r = m0 + wm + (mi << 4) + lr4;
#pragma unroll
        for (int ni = 0; ni < 4; ni++) {
            const int c = n0 + wn + (ni << 3) + lc2;
            const float bx = bias[c], by = bias[c + 1];
            const float v0 = (acc[mi][ni][0] + bx) * sc, v1 = (acc[mi][ni][1] + by) * sc;
            const float v2 = (acc[mi][ni][2] + bx) * sc, v3 = (acc[mi][ni][3] + by) * sc;
            *(uint32_t*)(Yh + (size_t)r * D_MODEL + c)       = pack2_hi_trunc(v0, v1);
            *(uint32_t*)(Yl + (size_t)r * D_MODEL + c)       = pack2_lo_trunc(v0, v1);
            *(uint32_t*)(Yh + (size_t)(r + 8) * D_MODEL + c) = pack2_hi_trunc(v2, v3);
            *(uint32_t*)(Yl + (size_t)(r + 8) * D_MODEL + c) = pack2_lo_trunc(v2, v3);
        }
    }
}

// ---- output projection, fp32 epilogue ----
__global__ __launch_bounds__(256, 2) void gemm_out_kernel(
    const float* __restrict__ bo, float* __restrict__ out)
{
    extern __shared__ char sm[];
    const uint32_t sb = smem_u32(sm);
    const int m0 = blockIdx.y << 7;
    const int n0 = blockIdx.x << 7;

    float acc[4][4][4] = {};
    gemm_core(g_Ch, g_Cl, g_Wh + 3 * NWE, g_Wl + 3 * NWE, sb, m0, n0, acc);

    const int lane = threadIdx.x & 31;
    const int wid  = threadIdx.x >> 5;
    const int wm   = (wid & 1) << 6;
    const int wn   = (wid >> 1) << 5;
    const int lr4  = lane >> 2;
    const int lc2  = (lane & 3) << 1;
#pragma unroll
    for (int mi = 0; mi < 4; mi++) {
        const int r = m0 + wm + (mi << 4) + lr4;
#pragma unroll
        for (int ni = 0; ni < 4; ni++) {
            const int c = n0 + wn + (ni << 3) + lc2;
            const float bx = bo[c], by = bo[c + 1];
            float2 o0, o1;
            o0.x = acc[mi][ni][0] + bx; o0.y = acc[mi][ni][1] + by;
            o1.x = acc[mi][ni][2] + bx; o1.y = acc[mi][ni][3] + by;
            *(float2*)(out + (size_t)r * D_MODEL + c)       = o0;
            *(float2*)(out + (size_t)(r + 8) * D_MODEL + c) = o1;
        }
    }
}

// ===========================================================================
// Tensor-core flash attention v7: 256 q-rows per CTA, 8 warps x 32 rows.
// 4-stage K/V pipeline, ONE barrier per PAIR of k-tiles: warps drift up to
// ~2 tiles so one warp's softmax overlaps another's MMAs. No-max exp2
// softmax (zero shuffles in loop); bit-packed mask; P packed on the fly.
// smem: Qh 32K | Ql 32K | 4 x stage(Kh 8K, Kl 8K, Vh 8K, Vl 8K) = 192 KB
// ===========================================================================
#define AS_QLO   32768
#define AS_STG   65536
#define AS_STGSZ 32768
#define AS_KLO   8192
#define AS_VHI   16384
#define AS_VLO   24576
#define ATT_SMEM 196608

__global__ __launch_bounds__(256, 1) void attn_mma_kernel()
{
    extern __shared__ char sm[];
    const uint32_t sb = smem_u32(sm);
    const int t    = threadIdx.x;
    const int lane = t & 31;
    const int w    = t >> 5;
    const int b  = blockIdx.z;
    const int h  = blockIdx.y;
    const int q0 = blockIdx.x << 8;          // 256 q rows per CTA
    const size_t bS   = (size_t)b * SEQ;
    const size_t hoff = (size_t)h * DK;

    const __nv_bfloat16* Qh = g_Ph;
    const __nv_bfloat16* Ql = g_Pl;
    const __nv_bfloat16* Kh = g_Ph + NXE;
    const __nv_bfloat16* Kl = g_Pl + NXE;
    const __nv_bfloat16* Vh = g_Ph + 2 * NXE;
    const __nv_bfloat16* Vl = g_Pl + 2 * NXE;

    auto issue_stage = [&](int kt) {
        const uint32_t base = sb + AS_STG + (kt & 3) * AS_STGSZ;
#pragma unroll
        for (int i = 0; i < 2; i++) {
            const int idx = t + (i << 8);
            const int row = idx >> 3, ch = idx & 7;
            const size_t go = (bS + (kt << 6) + row) * D_MODEL + hoff + (ch << 3);
            const uint32_t so = swz(row, ch);
            CP16(base + so,          Kh + go);
            CP16(base + AS_KLO + so, Kl + go);
            CP16(base + AS_VHI + so, Vh + go);
            CP16(base + AS_VLO + so, Vl + go);
        }
    };

    // prologue: group0 = Q + tiles 0,1 ; group1 = tiles 2,3
#pragma unroll
    for (int i = 0; i < 8; i++) {
        const int idx = t + (i << 8);
        const int row = idx >> 3, ch = idx & 7;
        const size_t go = (bS + q0 + row) * D_MODEL + hoff + (ch << 3);
        const uint32_t so = swz(row, ch);
        CP16(sb + so,          Qh + go);
        CP16(sb + AS_QLO + so, Ql + go);
    }
    issue_stage(0);
    issue_stage(1);
    CP_COMMIT;
    issue_stage(2);
    issue_stage(3);
    CP_COMMIT;
    CP_WAIT1;          // Q + tiles 0,1 ready
    __syncthreads();

    float O[2][8][4] = {};
    float ll[4] = {0.0f, 0.0f, 0.0f, 0.0f};   // per-thread partial row sums

    const int qr0 = q0 + (w << 5) + (lane >> 2);   // warp covers rows qr0..+24
    const int kc  = (lane & 3) << 1;

    auto process_tile = [&](int kt) {
        const uint32_t kb = sb + AS_STG + (kt & 3) * AS_STGSZ;

        // ---- mask prefetch: 4 u64 words (64 key-bits each) ----
        const uint64_t* Mb = g_maskb + (size_t)qr0 * (SEQ / 64) + kt;
        const uint64_t w0 = Mb[0] >> kc;
        const uint64_t w1 = Mb[(size_t)8  * (SEQ / 64)] >> kc;
        const uint64_t w2 = Mb[(size_t)16 * (SEQ / 64)] >> kc;
        const uint64_t w3 = Mb[(size_t)24 * (SEQ / 64)] >> kc;

        // ---- S = Q . K^T  (32 q rows x 64 keys per warp) ----
        float S[2][8][4] = {};
#pragma unroll
        for (int ks = 0; ks < 4; ks++) {
            uint32_t kh[4][4], kl[4][4];
#pragma unroll
            for (int g = 0; g < 4; g++) {
                const int nr = (g << 4) + (lane & 7) + ((lane >> 4) << 3);
                const int ch = (ks << 1) + ((lane >> 3) & 1);
                const uint32_t ka = kb + swz(nr, ch);
                LDM4(kh[g], ka);
                LDM4(kl[g], ka + AS_KLO);
            }
#pragma unroll
            for (int mi = 0; mi < 2; mi++) {
                uint32_t qh[4], ql[4];
                const int row = (w << 5) + (mi << 4) + (lane & 15);
                const int ch  = (ks << 1) + (lane >> 4);
                const uint32_t qa = sb + swz(row, ch);
                LDM4(qh, qa);
                LDM4(ql, qa + AS_QLO);
#pragma unroll
                for (int g = 0; g < 4; g++) {
                    MMA_BF16(S[mi][2 * g],     qh, kh[g][0], kh[g][1]);
                    MMA_BF16(S[mi][2 * g],     qh, kl[g][0], kl[g][1]);
                    MMA_BF16(S[mi][2 * g],     ql, kh[g][0], kh[g][1]);
                    MMA_BF16(S[mi][2 * g + 1], qh, kh[g][2], kh[g][3]);
                    MMA_BF16(S[mi][2 * g + 1], qh, kl[g][2], kl[g][3]);
                    MMA_BF16(S[mi][2 * g + 1], ql, kh[g][2], kh[g][3]);
                }
            }
        }

        // ---- P = exp2(S); masked -> e^-1; per-thread row-sum partials ----
#pragma unroll
        for (int mi = 0; mi < 2; mi++) {
            const uint64_t wa = mi ? w2 : w0;
            const uint64_t wb = mi ? w3 : w1;
            float rs0 = 0.0f, rs1 = 0.0f;
#pragma unroll
            for (int j = 0; j < 8; j++) {
                const float e0 = ex2f(S[mi][j][0]);
                const float e1 = ex2f(S[mi][j][1]);
                const float e2 = ex2f(S[mi][j][2]);
                const float e3 = ex2f(S[mi][j][3]);
                const uint32_t sa  = (uint32_t)(wa >> (8 * j));
                const uint32_t sbm = (uint32_t)(wb >> (8 * j));
                S[mi][j][0] = (sa  & 1) ? e0 : EXPN1;
                S[mi][j][1] = (sa  & 2) ? e1 : EXPN1;
                S[mi][j][2] = (sbm & 1) ? e2 : EXPN1;
                S[mi][j][3] = (sbm & 2) ? e3 : EXPN1;
                rs0 += S[mi][j][0] + S[mi][j][1];
                rs1 += S[mi][j][2] + S[mi][j][3];
            }
            ll[2 * mi]     += rs0;
            ll[2 * mi + 1] += rs1;
        }

        // ---- O += P . V  (P packed on the fly, per tt) ----
#pragma unroll
        for (int tt = 0; tt < 4; tt++) {
            uint32_t Pha[2][4], Pla[2][4];
#pragma unroll
            for (int mi = 0; mi < 2; mi++) {
                const float* p0 = S[mi][2 * tt];
                const float* p1 = S[mi][2 * tt + 1];
                Pha[mi][0] = pack2_hi_trunc(p0[0], p0[1]);
                Pha[mi][1] = pack2_hi_trunc(p0[2], p0[3]);
                Pha[mi][2] = pack2_hi_trunc(p1[0], p1[1]);
                Pha[mi][3] = pack2_hi_trunc(p1[2], p1[3]);
                Pla[mi][0] = pack2_lo_trunc(p0[0], p0[1]);
                Pla[mi][1] = pack2_lo_trunc(p0[2], p0[3]);
                Pla[mi][2] = pack2_lo_trunc(p1[0], p1[1]);
                Pla[mi][3] = pack2_lo_trunc(p1[2], p1[3]);
            }
#pragma unroll
            for (int g = 0; g < 4; g++) {
                const int row = (tt << 4) + (lane & 15);
                const int ch  = (g << 1) + (lane >> 4);
                const uint32_t va = kb + AS_VHI + swz(row, ch);
                uint32_t vh[4], vl[4];
                LDM4_T(vh, va);
                LDM4_T(vl, va + 8192);
#pragma unroll
                for (int mi = 0; mi < 2; mi++) {
                    MMA_BF16(O[mi][2 * g],     Pha[mi], vh[0], vh[1]);
                    MMA_BF16(O[mi][2 * g],     Pha[mi], vl[0], vl[1]);
                    MMA_BF16(O[mi][2 * g],     Pla[mi], vh[0], vh[1]);
                    MMA_BF16(O[mi][2 * g + 1], Pha[mi], vh[2], vh[3]);
                    MMA_BF16(O[mi][2 * g + 1], Pha[mi], vl[2], vl[3]);
                    MMA_BF16(O[mi][2 * g + 1], Pla[mi], vh[2], vh[3]);
                }
            }
        }
    };

    // main loop: one barrier per PAIR of tiles (16 pairs)
    for (int p = 0; p < SEQ / 128; p++) {
        process_tile(2 * p);
        process_tile(2 * p + 1);
        if (p < 15) {
            CP_WAIT0;                       // pair p+1 data landed
            __syncthreads();                // all warps done with pair p bufs
            if (p < 14) {
                issue_stage(2 * p + 4);     // refill pair-p buffers
                issue_stage(2 * p + 5);
                CP_COMMIT;
            }
        }
    }

    // ---- reduce row sums across the 4 lanes per row (once) ----
#pragma unroll
    for (int i = 0; i < 4; i++) {
        ll[i] += __shfl_xor_sync(0xffffffffu, ll[i], 1);
        ll[i] += __shfl_xor_sync(0xffffffffu, ll[i], 2);
    }

    // ---- normalize + write context as bf16 hi/lo planes [B,S,H*DK] ----
#pragma unroll
    for (int mi = 0; mi < 2; mi++) {
        const float i0 = 1.0f / ll[2 * mi];
        const float i1 = 1.0f / ll[2 * mi + 1];
        const size_t co0 = (bS + qr0 + (mi << 4)) * D_MODEL + hoff + kc;
        const size_t co1 = co0 + (size_t)8 * D_MODEL;
#pragma unroll
        for (int j = 0; j < 8; j++) {
            const float v0 = O[mi][j][0] * i0, v1 = O[mi][j][1] * i0;
            const float v2 = O[mi][j][2] * i1, v3 = O[mi][j][3] * i1;
            *(uint32_t*)(g_Ch + co0 + (j << 3)) = pack2_hi_trunc(v0, v1);
            *(uint32_t*)(g_Cl + co0 + (j << 3)) = pack2_lo_trunc(v0, v1);
            *(uint32_t*)(g_Ch + co1 + (j << 3)) = pack2_hi_trunc(v2, v3);
            *(uint32_t*)(g_Cl + co1 + (j << 3)) = pack2_lo_trunc(v2, v3);
        }
    }
}

// ---------------------------------------------------------------------------
extern "C" void kernel_launch(void* const* d_in, const int* in_sizes, int n_in,
                              void* d_out, int out_size)
{
    const float* q    = (const float*)d_in[0];
    const float* k    = (const float*)d_in[1];
    const float* v    = (const float*)d_in[2];
    const int*   mask = (const int*)  d_in[3];
    const float* wq   = (const float*)d_in[4];
    const float* bq   = (const float*)d_in[5];
    const float* wk   = (const float*)d_in[6];
    const float* bk   = (const float*)d_in[7];
    const float* wv   = (const float*)d_in[8];
    const float* bv   = (const float*)d_in[9];
    const float* wo   = (const float*)d_in[10];
    const float* bo   = (const float*)d_in[11];
    float* out = (float*)d_out;

    cudaFuncSetAttribute(gemm_qkv_kernel,
                         cudaFuncAttributeMaxDynamicSharedMemorySize, GEMM_SMEM);
    cudaFuncSetAttribute(gemm_out_kernel,
                         cudaFuncAttributeMaxDynamicSharedMemorySize, GEMM_SMEM);
    cudaFuncSetAttribute(attn_mma_kernel,
                         cudaFuncAttributeMaxDynamicSharedMemorySize, ATT_SMEM);

    // merged prepass: 3*4096 input + 4*1024 weight + 512 mask blocks
    split_all_kernel<<<16896, 256>>>(q, k, v, wq, wk, wv, wo, mask);

    gemm_qkv_kernel<<<dim3(8, 32, 3), 256, GEMM_SMEM>>>(bq, bk, bv);

    attn_mma_kernel<<<dim3(SEQ / 256, NHEAD, BATCH), 256, ATT_SMEM>>>();

    gemm_out_kernel<<<dim3(8, 32, 1), 256, GEMM_SMEM>>>(bo, out);
}

// round 14
// speedup vs baseline: 1.0743x; 1.0743x over previous
#include <cuda_runtime.h>
#include <cuda_bf16.h>
#include <cstdint>
#include <cstddef>

#define D_MODEL 1024
#define NHEAD   16
#define DK      64
#define BATCH   2
#define SEQ     2048
#define M_TOT   (BATCH * SEQ)                 // 4096
#define NXE     ((size_t)M_TOT * D_MODEL)     // 4M elems
#define NWE     ((size_t)D_MODEL * D_MODEL)   // 1M elems
#define LOG2E   1.4426950408889634f
#define EXPN1   0.36787944117144233f          // e^-1 (masked-score weight)

// Scratch (allocation-free: __device__ globals)
__device__ __nv_bfloat16 g_INh[3 * NXE];   // split q,k,v inputs (hi)
__device__ __nv_bfloat16 g_INl[3 * NXE];   // (lo)
__device__ __nv_bfloat16 g_Wh[4 * NWE];    // split wq,wk,wv,wo (hi)
__device__ __nv_bfloat16 g_Wl[4 * NWE];    // (lo)
__device__ __nv_bfloat16 g_Ph[3 * NXE];    // projected Q (rn bf16), K, V (hi)
__device__ __nv_bfloat16 g_Pl[3 * NXE];    // (lo; Q region unused)
__device__ __nv_bfloat16 g_Ch[NXE];        // attention context (hi)
__device__ __nv_bfloat16 g_Cl[NXE];        // (lo)
__device__ uint64_t      g_maskb[(size_t)SEQ * SEQ / 64];  // bit-packed mask

// ===========================================================================
// Helpers (baseline PTX ISA only — compute_103-safe)
// ===========================================================================
__device__ __forceinline__ uint32_t smem_u32(const void* p) {
    uint32_t a;
    asm("{ .reg .u64 t; cvta.to.shared.u64 t, %1; cvt.u32.u64 %0, t; }"
        : "=r"(a) : "l"(p));
    return a;
}

__device__ __forceinline__ float ex2f(float x) {
    float y;
    asm("ex2.approx.f32 %0, %1;" : "=f"(y) : "f"(x));
    return y;
}

#define LDM4(r, addr) \
    asm volatile("ldmatrix.sync.aligned.m8n8.x4.shared.b16 {%0,%1,%2,%3}, [%4];" \
        : "=r"((r)[0]), "=r"((r)[1]), "=r"((r)[2]), "=r"((r)[3]) : "r"(addr))

#define LDM4_T(r, addr) \
    asm volatile("ldmatrix.sync.aligned.m8n8.x4.trans.shared.b16 {%0,%1,%2,%3}, [%4];" \
        : "=r"((r)[0]), "=r"((r)[1]), "=r"((r)[2]), "=r"((r)[3]) : "r"(addr))

#define MMA_BF16(d, a, b0, b1) \
    asm volatile("mma.sync.aligned.m16n8k16.row.col.f32.bf16.bf16.f32 " \
        "{%0,%1,%2,%3}, {%4,%5,%6,%7}, {%8,%9}, {%0,%1,%2,%3};" \
        : "+f"((d)[0]), "+f"((d)[1]), "+f"((d)[2]), "+f"((d)[3]) \
        : "r"((a)[0]), "r"((a)[1]), "r"((a)[2]), "r"((a)[3]), "r"(b0), "r"(b1))

#define CP16(sa, gp) \
    asm volatile("{ .reg .u64 g; cvta.to.global.u64 g, %1; " \
                 "cp.async.cg.shared.global [%0], [g], 16; }" \
        :: "r"((uint32_t)(sa)), "l"(gp) : "memory")
#define CP_COMMIT  asm volatile("cp.async.commit_group;" ::: "memory")
#define CP_WAIT1   asm volatile("cp.async.wait_group 1;" ::: "memory")
#define CP_WAIT0   asm volatile("cp.async.wait_group 0;" ::: "memory")

__device__ __forceinline__ uint32_t pack_bf16(float a, float b) {
    __nv_bfloat162 h = __floats2bfloat162_rn(a, b);
    return *(uint32_t*)&h;
}
// Truncation split: hi = top 16 bits of fp32, lo = exact residual rounded.
__device__ __forceinline__ uint32_t pack2_hi_trunc(float a, float b) {
    return __byte_perm(__float_as_uint(a), __float_as_uint(b), 0x7632);
}
__device__ __forceinline__ uint32_t pack2_lo_trunc(float a, float b) {
    float ah = __uint_as_float(__float_as_uint(a) & 0xFFFF0000u);
    float bh = __uint_as_float(__float_as_uint(b) & 0xFFFF0000u);
    return pack_bf16(a - ah, b - bh);
}
__device__ __forceinline__ void cvt4_split(float4 f, uint2& hi, uint2& lo) {
    hi.x = pack2_hi_trunc(f.x, f.y);  hi.y = pack2_hi_trunc(f.z, f.w);
    lo.x = pack2_lo_trunc(f.x, f.y);  lo.y = pack2_lo_trunc(f.z, f.w);
}

// XOR swizzle: 128B rows, 16B chunks permuted within row (ldmatrix-safe)
__device__ __forceinline__ uint32_t swz(uint32_t row, uint32_t chunk) {
    return (row << 7) + ((chunk ^ (row & 7)) << 4);
}

// ===========================================================================
// Merged pre-pass: splits q,k,v (3 x 4096 blocks), wq..wo (4 x 1024 blocks),
// and bit-packs the mask (512 blocks at the end).
// ===========================================================================
__global__ void split_all_kernel(
    const float* __restrict__ q,  const float* __restrict__ k,
    const float* __restrict__ v,
    const float* __restrict__ w0, const float* __restrict__ w1,
    const float* __restrict__ w2, const float* __restrict__ w3,
    const int*   __restrict__ m)
{
    const int blk = blockIdx.x;
    if (blk >= 16384) {                      // mask bit-pack: 512 blocks
        const size_t tid  = (size_t)(blk - 16384) * 256 + threadIdx.x;
        const size_t base = tid << 5;        // 32 consecutive ints
        uint32_t bits = 0;
#pragma unroll
        for (int i = 0; i < 8; i++) {
            int4 vv = *(const int4*)(m + base + (i << 2));
            bits |= (vv.x ? 1u : 0u) << (4 * i);
            bits |= (vv.y ? 1u : 0u) << (4 * i + 1);
            bits |= (vv.z ? 1u : 0u) << (4 * i + 2);
            bits |= (vv.w ? 1u : 0u) << (4 * i + 3);
        }
        ((uint32_t*)g_maskb)[tid] = bits;
        return;
    }
    const float* src;
    __nv_bfloat16 *dh, *dl;
    size_t i;
    if (blk < 12288) {                       // inputs: 3 x 4096 blocks
        const int z = blk >> 12;
        src = (z == 0) ? q : (z == 1) ? k : v;
        i = ((size_t)(blk & 4095) * 256 + threadIdx.x) << 2;
        dh = g_INh + (size_t)z * NXE;
        dl = g_INl + (size_t)z * NXE;
    } else {                                 // weights: 4 x 1024 blocks
        const int wblk = blk - 12288;
        const int z = wblk >> 10;
        src = (z == 0) ? w0 : (z == 1) ? w1 : (z == 2) ? w2 : w3;
        i = ((size_t)(wblk & 1023) * 256 + threadIdx.x) << 2;
        dh = g_Wh + (size_t)z * NWE;
        dl = g_Wl + (size_t)z * NWE;
    }
    float4 f = *(const float4*)(src + i);
    uint2 hi, lo; cvt4_split(f, hi, lo);
    *(uint2*)(dh + i) = hi;
    *(uint2*)(dl + i) = lo;
}

// ===========================================================================
// GEMM core (pre-split bf16 operands, cp.async 3-stage pipeline)
// CTA tile 128x128, BK=32. smem stage 32K: A(hi|lo packed rows) 16K + B 16K.
// ===========================================================================
#define GSTG      32768
#define GEMM_SMEM (3 * GSTG)   // 98304

__device__ __forceinline__ void gemm_core(
    const __nv_bfloat16* __restrict__ Xh, const __nv_bfloat16* __restrict__ Xl,
    const __nv_bfloat16* __restrict__ Wh, const __nv_bfloat16* __restrict__ Wl,
    uint32_t sb, int m0, int n0, float (&acc)[4][4][4])
{
    const int t    = threadIdx.x;
    const int lane = t & 31;
    const int wid  = t >> 5;
    const int wm   = (wid & 1) << 6;
    const int wn   = (wid >> 1) << 5;

    auto issue = [&](int kt, int s) {
        const uint32_t base = sb + s * GSTG;
        const int k0 = kt << 5;
#pragma unroll
        for (int i = 0; i < 4; i++) {
            const int idx = t + (i << 8);
            const int row = idx >> 3, ch = idx & 7;
            const __nv_bfloat16* px = (ch < 4) ? Xh : Xl;
            const __nv_bfloat16* pw = (ch < 4) ? Wh : Wl;
            const int cc = (ch & 3) << 3;
            const uint32_t so = swz(row, ch);
            CP16(base + so,         px + (size_t)(m0 + row) * D_MODEL + k0 + cc);
            CP16(base + 16384 + so, pw + (size_t)(n0 + row) * D_MODEL + k0 + cc);
        }
    };

    issue(0, 0); CP_COMMIT;
    issue(1, 1); CP_COMMIT;

    for (int kt = 0; kt < 32; kt++) {
        if (kt < 30) { CP_WAIT1; } else { CP_WAIT0; }
        __syncthreads();
        if (kt < 30) { issue(kt + 2, (kt + 2) % 3); CP_COMMIT; }

        const uint32_t abuf = sb + (kt % 3) * GSTG;
        const uint32_t bbuf = abuf + 16384;
#pragma unroll
        for (int ks = 0; ks < 2; ks++) {
            uint32_t bh[4][2], bl[4][2];
#pragma unroll
            for (int p = 0; p < 2; p++) {
                const int nr = wn + (p << 4) + (lane & 7) + ((lane >> 4) << 3);
                const int ch = (ks << 1) + ((lane >> 3) & 1);
                uint32_t qq[4];
                LDM4(qq, bbuf + swz(nr, ch));
                bh[2 * p][0] = qq[0]; bh[2 * p][1] = qq[1];
                bh[2 * p + 1][0] = qq[2]; bh[2 * p + 1][1] = qq[3];
                LDM4(qq, bbuf + swz(nr, ch + 4));
                bl[2 * p][0] = qq[0]; bl[2 * p][1] = qq[1];
                bl[2 * p + 1][0] = qq[2]; bl[2 * p + 1][1] = qq[3];
            }
#pragma unroll
            for (int mi = 0; mi < 4; mi++) {
                const int row = wm + (mi << 4) + (lane & 15);
                const int ch  = (ks << 1) + (lane >> 4);
                uint32_t ah[4], al[4];
                LDM4(ah, abuf + swz(row, ch));
                LDM4(al, abuf + swz(row, ch + 4));
#pragma unroll
                for (int ni = 0; ni < 4; ni++) {
                    MMA_BF16(acc[mi][ni], ah, bh[ni][0], bh[ni][1]);
                    MMA_BF16(acc[mi][ni], ah, bl[ni][0], bl[ni][1]);
                    MMA_BF16(acc[mi][ni], al, bh[ni][0], bh[ni][1]);
                }
            }
        }
    }
}

// ---- batched Q/K/V projections. Q (z==0) pre-scaled by 0.125*log2(e) and
//      stored as a SINGLE rn-rounded bf16 plane (no lo); K/V keep hi/lo. ----
__global__ __launch_bounds__(256, 2) void gemm_qkv_kernel(
    const float* __restrict__ bq, const float* __restrict__ bk,
    const float* __restrict__ bv)
{
    extern __shared__ char sm[];
    const uint32_t sb = smem_u32(sm);
    const int z  = blockIdx.z;
    const int m0 = blockIdx.y << 7;
    const int n0 = blockIdx.x << 7;
    const size_t zo = (size_t)z * NXE;

    float acc[4][4][4] = {};
    gemm_core(g_INh + zo, g_INl + zo,
              g_Wh + (size_t)z * NWE, g_Wl + (size_t)z * NWE,
              sb, m0, n0, acc);

    const float* bias = (z == 0) ? bq : (z == 1) ? bk : bv;
    const float sc = (z == 0) ? (0.125f * LOG2E) : 1.0f;
    __nv_bfloat16* Yh = g_Ph + zo;
    __nv_bfloat16* Yl = g_Pl + zo;

    const int lane = threadIdx.x & 31;
    const int wid  = threadIdx.x >> 5;
    const int wm   = (wid & 1) << 6;
    const int wn   = (wid >> 1) << 5;
    const int lr4  = lane >> 2;
    const int lc2  = (lane & 3) << 1;
#pragma unroll
    for (int mi = 0; mi < 4; mi++) {
        const int r = m0 + wm + (mi << 4) + lr4;
#pragma unroll
        for (int ni = 0; ni < 4; ni++) {
            const int c = n0 + wn + (ni << 3) + lc2;
            const float bx = bias[c], by = bias[c + 1];
            const float v0 = (acc[mi][ni][0] + bx) * sc, v1 = (acc[mi][ni][1] + by) * sc;
            const float v2 = (acc[mi][ni][2] + bx) * sc, v3 = (acc[mi][ni][3] + by) * sc;
            if (z == 0) {
                // Q: single rn plane (residual <= 2^-9 relative, symmetric)
                *(uint32_t*)(Yh + (size_t)r * D_MODEL + c)       = pack_bf16(v0, v1);
                *(uint32_t*)(Yh + (size_t)(r + 8) * D_MODEL + c) = pack_bf16(v2, v3);
            } else {
                *(uint32_t*)(Yh + (size_t)r * D_MODEL + c)       = pack2_hi_trunc(v0, v1);
                *(uint32_t*)(Yl + (size_t)r * D_MODEL + c)       = pack2_lo_trunc(v0, v1);
                *(uint32_t*)(Yh + (size_t)(r + 8) * D_MODEL + c) = pack2_hi_trunc(v2, v3);
                *(uint32_t*)(Yl + (size_t)(r + 8) * D_MODEL + c) = pack2_lo_trunc(v2, v3);
            }
        }
    }
}

// ---- output projection, fp32 epilogue ----
__global__ __launch_bounds__(256, 2) void gemm_out_kernel(
    const float* __restrict__ bo, float* __restrict__ out)
{
    extern __shared__ char sm[];
    const uint32_t sb = smem_u32(sm);
    const int m0 = blockIdx.y << 7;
    const int n0 = blockIdx.x << 7;

    float acc[4][4][4] = {};
    gemm_core(g_Ch, g_Cl, g_Wh + 3 * NWE, g_Wl + 3 * NWE, sb, m0, n0, acc);

    const int lane = threadIdx.x & 31;
    const int wid  = threadIdx.x >> 5;
    const int wm   = (wid & 1) << 6;
    const int wn   = (wid >> 1) << 5;
    const int lr4  = lane >> 2;
    const int lc2  = (lane & 3) << 1;
#pragma unroll
    for (int mi = 0; mi < 4; mi++) {
        const int r = m0 + wm + (mi << 4) + lr4;
#pragma unroll
        for (int ni = 0; ni < 4; ni++) {
            const int c = n0 + wn + (ni << 3) + lc2;
            const float bx = bo[c], by = bo[c + 1];
            float2 o0, o1;
            o0.x = acc[mi][ni][0] + bx; o0.y = acc[mi][ni][1] + by;
            o1.x = acc[mi][ni][2] + bx; o1.y = acc[mi][ni][3] + by;
            *(float2*)(out + (size_t)r * D_MODEL + c)       = o0;
            *(float2*)(out + (size_t)(r + 8) * D_MODEL + c) = o1;
        }
    }
}

// ===========================================================================
// Tensor-core flash attention v8: 256 q-rows per CTA, 8 warps x 32 rows.
// Q is a single rn bf16 plane -> QK needs only 2 MMAs (Qh.Kh + Qh.Kl):
// attention MMA count drops 384 -> 320 per tile (-17%), Q ldmatrix halves,
// Q smem halves. No-max exp2 softmax (zero shuffles); bit-packed mask;
// one __syncthreads per k-tile; P packed on the fly (3-term PV kept).
// smem: Q 32K | 2 x stage(Kh 8K, Kl 8K, Vh 8K, Vl 8K) = 96 KB
// ===========================================================================
#define AS_STG   32768
#define AS_STGSZ 32768
#define AS_KLO   8192
#define AS_VHI   16384
#define AS_VLO   24576
#define ATT_SMEM 98304

__global__ __launch_bounds__(256, 1) void attn_mma_kernel()
{
    extern __shared__ char sm[];
    const uint32_t sb = smem_u32(sm);
    const int t    = threadIdx.x;
    const int lane = t & 31;
    const int w    = t >> 5;
    const int b  = blockIdx.z;
    const int h  = blockIdx.y;
    const int q0 = blockIdx.x << 8;          // 256 q rows per CTA
    const size_t bS   = (size_t)b * SEQ;
    const size_t hoff = (size_t)h * DK;

    const __nv_bfloat16* Qp = g_Ph;
    const __nv_bfloat16* Kh = g_Ph + NXE;
    const __nv_bfloat16* Kl = g_Pl + NXE;
    const __nv_bfloat16* Vh = g_Ph + 2 * NXE;
    const __nv_bfloat16* Vl = g_Pl + 2 * NXE;

    auto issue_stage = [&](int kt, int bufsel) {
        const uint32_t base = sb + AS_STG + bufsel * AS_STGSZ;
#pragma unroll
        for (int i = 0; i < 2; i++) {
            const int idx = t + (i << 8);
            const int row = idx >> 3, ch = idx & 7;
            const size_t go = (bS + (kt << 6) + row) * D_MODEL + hoff + (ch << 3);
            const uint32_t so = swz(row, ch);
            CP16(base + so,          Kh + go);
            CP16(base + AS_KLO + so, Kl + go);
            CP16(base + AS_VHI + so, Vh + go);
            CP16(base + AS_VLO + so, Vl + go);
        }
    };

    // prologue: Q tile (256 rows, single plane) + stage0; stage1 in group B
#pragma unroll
    for (int i = 0; i < 8; i++) {
        const int idx = t + (i << 8);
        const int row = idx >> 3, ch = idx & 7;
        const size_t go = (bS + q0 + row) * D_MODEL + hoff + (ch << 3);
        CP16(sb + swz(row, ch), Qp + go);
    }
    issue_stage(0, 0);
    CP_COMMIT;
    issue_stage(1, 1);
    CP_COMMIT;
    CP_WAIT1;
    __syncthreads();

    float O[2][8][4] = {};
    float ll[4] = {0.0f, 0.0f, 0.0f, 0.0f};   // per-thread partial row sums

    const int qr0 = q0 + (w << 5) + (lane >> 2);   // warp covers rows qr0..+24
    const int kc  = (lane & 3) << 1;

    for (int kt = 0; kt < SEQ / 64; kt++) {
        const uint32_t kb = sb + AS_STG + (kt & 1) * AS_STGSZ;

        // ---- mask prefetch: 4 u64 words (64 key-bits each) ----
        const uint64_t* Mb = g_maskb + (size_t)qr0 * (SEQ / 64) + kt;
        const uint64_t w0 = Mb[0] >> kc;
        const uint64_t w1 = Mb[(size_t)8  * (SEQ / 64)] >> kc;
        const uint64_t w2 = Mb[(size_t)16 * (SEQ / 64)] >> kc;
        const uint64_t w3 = Mb[(size_t)24 * (SEQ / 64)] >> kc;

        // ---- S = Q . K^T  (32 q rows x 64 keys per warp; 2-term split) ----
        float S[2][8][4] = {};
#pragma unroll
        for (int ks = 0; ks < 4; ks++) {
            uint32_t kh[4][4], kl[4][4];
#pragma unroll
            for (int g = 0; g < 4; g++) {
                const int nr = (g << 4) + (lane & 7) + ((lane >> 4) << 3);
                const int ch = (ks << 1) + ((lane >> 3) & 1);
                const uint32_t ka = kb + swz(nr, ch);
                LDM4(kh[g], ka);
                LDM4(kl[g], ka + AS_KLO);
            }
#pragma unroll
            for (int mi = 0; mi < 2; mi++) {
                uint32_t qh[4];
                const int row = (w << 5) + (mi << 4) + (lane & 15);
                const int ch  = (ks << 1) + (lane >> 4);
                LDM4(qh, sb + swz(row, ch));
#pragma unroll
                for (int g = 0; g < 4; g++) {
                    MMA_BF16(S[mi][2 * g],     qh, kh[g][0], kh[g][1]);
                    MMA_BF16(S[mi][2 * g],     qh, kl[g][0], kl[g][1]);
                    MMA_BF16(S[mi][2 * g + 1], qh, kh[g][2], kh[g][3]);
                    MMA_BF16(S[mi][2 * g + 1], qh, kl[g][2], kl[g][3]);
                }
            }
        }

        // ---- P = exp2(S); masked -> e^-1; per-thread row-sum partials ----
#pragma unroll
        for (int mi = 0; mi < 2; mi++) {
            const uint64_t wa = mi ? w2 : w0;
            const uint64_t wb = mi ? w3 : w1;
            float rs0 = 0.0f, rs1 = 0.0f;
#pragma unroll
            for (int j = 0; j < 8; j++) {
                const float e0 = ex2f(S[mi][j][0]);
                const float e1 = ex2f(S[mi][j][1]);
                const float e2 = ex2f(S[mi][j][2]);
                const float e3 = ex2f(S[mi][j][3]);
                const uint32_t sa  = (uint32_t)(wa >> (8 * j));
                const uint32_t sbm = (uint32_t)(wb >> (8 * j));
                S[mi][j][0] = (sa  & 1) ? e0 : EXPN1;
                S[mi][j][1] = (sa  & 2) ? e1 : EXPN1;
                S[mi][j][2] = (sbm & 1) ? e2 : EXPN1;
                S[mi][j][3] = (sbm & 2) ? e3 : EXPN1;
                rs0 += S[mi][j][0] + S[mi][j][1];
                rs1 += S[mi][j][2] + S[mi][j][3];
            }
            ll[2 * mi]     += rs0;
            ll[2 * mi + 1] += rs1;
        }

        // ---- O += P . V  (P packed on the fly; full 3-term split) ----
#pragma unroll
        for (int tt = 0; tt < 4; tt++) {
            uint32_t Pha[2][4], Pla[2][4];
#pragma unroll
            for (int mi = 0; mi < 2; mi++) {
                const float* p0 = S[mi][2 * tt];
                const float* p1 = S[mi][2 * tt + 1];
                Pha[mi][0] = pack2_hi_trunc(p0[0], p0[1]);
                Pha[mi][1] = pack2_hi_trunc(p0[2], p0[3]);
                Pha[mi][2] = pack2_hi_trunc(p1[0], p1[1]);
                Pha[mi][3] = pack2_hi_trunc(p1[2], p1[3]);
                Pla[mi][0] = pack2_lo_trunc(p0[0], p0[1]);
                Pla[mi][1] = pack2_lo_trunc(p0[2], p0[3]);
                Pla[mi][2] = pack2_lo_trunc(p1[0], p1[1]);
                Pla[mi][3] = pack2_lo_trunc(p1[2], p1[3]);
            }
#pragma unroll
            for (int g = 0; g < 4; g++) {
                const int row = (tt << 4) + (lane & 15);
                const int ch  = (g << 1) + (lane >> 4);
                const uint32_t va = kb + AS_VHI + swz(row, ch);
                uint32_t vh[4], vl[4];
                LDM4_T(vh, va);
                LDM4_T(vl, va + 8192);
#pragma unroll
                for (int mi = 0; mi < 2; mi++) {
                    MMA_BF16(O[mi][2 * g],     Pha[mi], vh[0], vh[1]);
                    MMA_BF16(O[mi][2 * g],     Pha[mi], vl[0], vl[1]);
                    MMA_BF16(O[mi][2 * g],     Pla[mi], vh[0], vh[1]);
                    MMA_BF16(O[mi][2 * g + 1], Pha[mi], vh[2], vh[3]);
                    MMA_BF16(O[mi][2 * g + 1], Pha[mi], vl[2], vl[3]);
                    MMA_BF16(O[mi][2 * g + 1], Pla[mi], vh[2], vh[3]);
                }
            }
        }

        // ---- pipeline advance: ONE barrier per kt ----
        if (kt < 31) {
            CP_WAIT0;
            __syncthreads();
            if (kt < 30) {
                issue_stage(kt + 2, kt & 1);
                CP_COMMIT;
            }
        }
    }

    // ---- reduce row sums across the 4 lanes per row (once) ----
#pragma unroll
    for (int i = 0; i < 4; i++) {
        ll[i] += __shfl_xor_sync(0xffffffffu, ll[i], 1);
        ll[i] += __shfl_xor_sync(0xffffffffu, ll[i], 2);
    }

    // ---- normalize + write context as bf16 hi/lo planes [B,S,H*DK] ----
#pragma unroll
    for (int mi = 0; mi < 2; mi++) {
        const float i0 = 1.0f / ll[2 * mi];
        const float i1 = 1.0f / ll[2 * mi + 1];
        const size_t co0 = (bS + qr0 + (mi << 4)) * D_MODEL + hoff + kc;
        const size_t co1 = co0 + (size_t)8 * D_MODEL;
#pragma unroll
        for (int j = 0; j < 8; j++) {
            const float v0 = O[mi][j][0] * i0, v1 = O[mi][j][1] * i0;
            const float v2 = O[mi][j][2] * i1, v3 = O[mi][j][3] * i1;
            *(uint32_t*)(g_Ch + co0 + (j << 3)) = pack2_hi_trunc(v0, v1);
            *(uint32_t*)(g_Cl + co0 + (j << 3)) = pack2_lo_trunc(v0, v1);
            *(uint32_t*)(g_Ch + co1 + (j << 3)) = pack2_hi_trunc(v2, v3);
            *(uint32_t*)(g_Cl + co1 + (j << 3)) = pack2_lo_trunc(v2, v3);
        }
    }
}

// ---------------------------------------------------------------------------
extern "C" void kernel_launch(void* const* d_in, const int* in_sizes, int n_in,
                              void* d_out, int out_size)
{
    const float* q    = (const float*)d_in[0];
    const float* k    = (const float*)d_in[1];
    const float* v    = (const float*)d_in[2];
    const int*   mask = (const int*)  d_in[3];
    const float* wq   = (const float*)d_in[4];
    const float* bq   = (const float*)d_in[5];
    const float* wk   = (const float*)d_in[6];
    const float* bk   = (const float*)d_in[7];
    const float* wv   = (const float*)d_in[8];
    const float* bv   = (const float*)d_in[9];
    const float* wo   = (const float*)d_in[10];
    const float* bo   = (const float*)d_in[11];
    float* out = (float*)d_out;

    cudaFuncSetAttribute(gemm_qkv_kernel,
                         cudaFuncAttributeMaxDynamicSharedMemorySize, GEMM_SMEM);
    cudaFuncSetAttribute(gemm_out_kernel,
                         cudaFuncAttributeMaxDynamicSharedMemorySize, GEMM_SMEM);
    cudaFuncSetAttribute(attn_mma_kernel,
                         cudaFuncAttributeMaxDynamicSharedMemorySize, ATT_SMEM);

    // merged prepass: 3*4096 input + 4*1024 weight + 512 mask blocks
    split_all_kernel<<<16896, 256>>>(q, k, v, wq, wk, wv, wo, mask);

    gemm_qkv_kernel<<<dim3(8, 32, 3), 256, GEMM_SMEM>>>(bq, bk, bv);

    attn_mma_kernel<<<dim3(SEQ / 256, NHEAD, BATCH), 256, ATT_SMEM>>>();

    gemm_out_kernel<<<dim3(8, 32, 1), 256, GEMM_SMEM>>>(bo, out);
}

// round 15
// speedup vs baseline: 1.1422x; 1.0632x over previous
#include <cuda_runtime.h>
#include <cuda_bf16.h>
#include <cstdint>
#include <cstddef>

#define D_MODEL 1024
#define NHEAD   16
#define DK      64
#define BATCH   2
#define SEQ     2048
#define M_TOT   (BATCH * SEQ)                 // 4096
#define NXE     ((size_t)M_TOT * D_MODEL)     // 4M elems
#define NWE     ((size_t)D_MODEL * D_MODEL)   // 1M elems
#define LOG2E   1.4426950408889634f
#define EXPN1   0.36787944117144233f          // e^-1 (masked-score weight)

// Scratch (allocation-free: __device__ globals)
__device__ __nv_bfloat16 g_INh[3 * NXE];   // split q,k,v inputs (hi)
__device__ __nv_bfloat16 g_INl[3 * NXE];   // (lo)
__device__ __nv_bfloat16 g_Wh[4 * NWE];    // split wq,wk,wv,wo (hi)
__device__ __nv_bfloat16 g_Wl[4 * NWE];    // (lo)
__device__ __nv_bfloat16 g_Ph[3 * NXE];    // projected Q,K (rn bf16), V (hi)
__device__ __nv_bfloat16 g_Pl[3 * NXE];    // (lo; Q,K regions unused)
__device__ __nv_bfloat16 g_Ch[NXE];        // attention context (hi)
__device__ __nv_bfloat16 g_Cl[NXE];        // (lo)
__device__ uint64_t      g_maskb[(size_t)SEQ * SEQ / 64];  // bit-packed mask

// ===========================================================================
// Helpers (baseline PTX ISA only — compute_103-safe)
// ===========================================================================
__device__ __forceinline__ uint32_t smem_u32(const void* p) {
    uint32_t a;
    asm("{ .reg .u64 t; cvta.to.shared.u64 t, %1; cvt.u32.u64 %0, t; }"
        : "=r"(a) : "l"(p));
    return a;
}

__device__ __forceinline__ float ex2f(float x) {
    float y;
    asm("ex2.approx.f32 %0, %1;" : "=f"(y) : "f"(x));
    return y;
}

#define LDM4(r, addr) \
    asm volatile("ldmatrix.sync.aligned.m8n8.x4.shared.b16 {%0,%1,%2,%3}, [%4];" \
        : "=r"((r)[0]), "=r"((r)[1]), "=r"((r)[2]), "=r"((r)[3]) : "r"(addr))

#define LDM4_T(r, addr) \
    asm volatile("ldmatrix.sync.aligned.m8n8.x4.trans.shared.b16 {%0,%1,%2,%3}, [%4];" \
        : "=r"((r)[0]), "=r"((r)[1]), "=r"((r)[2]), "=r"((r)[3]) : "r"(addr))

#define MMA_BF16(d, a, b0, b1) \
    asm volatile("mma.sync.aligned.m16n8k16.row.col.f32.bf16.bf16.f32 " \
        "{%0,%1,%2,%3}, {%4,%5,%6,%7}, {%8,%9}, {%0,%1,%2,%3};" \
        : "+f"((d)[0]), "+f"((d)[1]), "+f"((d)[2]), "+f"((d)[3]) \
        : "r"((a)[0]), "r"((a)[1]), "r"((a)[2]), "r"((a)[3]), "r"(b0), "r"(b1))

#define CP16(sa, gp) \
    asm volatile("{ .reg .u64 g; cvta.to.global.u64 g, %1; " \
                 "cp.async.cg.shared.global [%0], [g], 16; }" \
        :: "r"((uint32_t)(sa)), "l"(gp) : "memory")
#define CP_COMMIT  asm volatile("cp.async.commit_group;" ::: "memory")
#define CP_WAIT1   asm volatile("cp.async.wait_group 1;" ::: "memory")
#define CP_WAIT0   asm volatile("cp.async.wait_group 0;" ::: "memory")

__device__ __forceinline__ uint32_t pack_bf16(float a, float b) {
    __nv_bfloat162 h = __floats2bfloat162_rn(a, b);
    return *(uint32_t*)&h;
}
// Truncation split: hi = top 16 bits of fp32, lo = exact residual rounded.
__device__ __forceinline__ uint32_t pack2_hi_trunc(float a, float b) {
    return __byte_perm(__float_as_uint(a), __float_as_uint(b), 0x7632);
}
__device__ __forceinline__ uint32_t pack2_lo_trunc(float a, float b) {
    float ah = __uint_as_float(__float_as_uint(a) & 0xFFFF0000u);
    float bh = __uint_as_float(__float_as_uint(b) & 0xFFFF0000u);
    return pack_bf16(a - ah, b - bh);
}
__device__ __forceinline__ void cvt4_split(float4 f, uint2& hi, uint2& lo) {
    hi.x = pack2_hi_trunc(f.x, f.y);  hi.y = pack2_hi_trunc(f.z, f.w);
    lo.x = pack2_lo_trunc(f.x, f.y);  lo.y = pack2_lo_trunc(f.z, f.w);
}

// XOR swizzle: 128B rows, 16B chunks permuted within row (ldmatrix-safe)
__device__ __forceinline__ uint32_t swz(uint32_t row, uint32_t chunk) {
    return (row << 7) + ((chunk ^ (row & 7)) << 4);
}

// ===========================================================================
// Merged pre-pass: splits q,k,v (3 x 4096 blocks), wq..wo (4 x 1024 blocks),
// and bit-packs the mask (512 blocks at the end).
// ===========================================================================
__global__ void split_all_kernel(
    const float* __restrict__ q,  const float* __restrict__ k,
    const float* __restrict__ v,
    const float* __restrict__ w0, const float* __restrict__ w1,
    const float* __restrict__ w2, const float* __restrict__ w3,
    const int*   __restrict__ m)
{
    const int blk = blockIdx.x;
    if (blk >= 16384) {                      // mask bit-pack: 512 blocks
        const size_t tid  = (size_t)(blk - 16384) * 256 + threadIdx.x;
        const size_t base = tid << 5;        // 32 consecutive ints
        uint32_t bits = 0;
#pragma unroll
        for (int i = 0; i < 8; i++) {
            int4 vv = *(const int4*)(m + base + (i << 2));
            bits |= (vv.x ? 1u : 0u) << (4 * i);
            bits |= (vv.y ? 1u : 0u) << (4 * i + 1);
            bits |= (vv.z ? 1u : 0u) << (4 * i + 2);
            bits |= (vv.w ? 1u : 0u) << (4 * i + 3);
        }
        ((uint32_t*)g_maskb)[tid] = bits;
        return;
    }
    const float* src;
    __nv_bfloat16 *dh, *dl;
    size_t i;
    if (blk < 12288) {                       // inputs: 3 x 4096 blocks
        const int z = blk >> 12;
        src = (z == 0) ? q : (z == 1) ? k : v;
        i = ((size_t)(blk & 4095) * 256 + threadIdx.x) << 2;
        dh = g_INh + (size_t)z * NXE;
        dl = g_INl + (size_t)z * NXE;
    } else {                                 // weights: 4 x 1024 blocks
        const int wblk = blk - 12288;
        const int z = wblk >> 10;
        src = (z == 0) ? w0 : (z == 1) ? w1 : (z == 2) ? w2 : w3;
        i = ((size_t)(wblk & 1023) * 256 + threadIdx.x) << 2;
        dh = g_Wh + (size_t)z * NWE;
        dl = g_Wl + (size_t)z * NWE;
    }
    float4 f = *(const float4*)(src + i);
    uint2 hi, lo; cvt4_split(f, hi, lo);
    *(uint2*)(dh + i) = hi;
    *(uint2*)(dl + i) = lo;
}

// ===========================================================================
// GEMM core (pre-split bf16 operands, cp.async 3-stage pipeline)
// CTA tile 128x128, BK=32. smem stage 32K: A(hi|lo packed rows) 16K + B 16K.
// ===========================================================================
#define GSTG      32768
#define GEMM_SMEM (3 * GSTG)   // 98304

__device__ __forceinline__ void gemm_core(
    const __nv_bfloat16* __restrict__ Xh, const __nv_bfloat16* __restrict__ Xl,
    const __nv_bfloat16* __restrict__ Wh, const __nv_bfloat16* __restrict__ Wl,
    uint32_t sb, int m0, int n0, float (&acc)[4][4][4])
{
    const int t    = threadIdx.x;
    const int lane = t & 31;
    const int wid  = t >> 5;
    const int wm   = (wid & 1) << 6;
    const int wn   = (wid >> 1) << 5;

    auto issue = [&](int kt, int s) {
        const uint32_t base = sb + s * GSTG;
        const int k0 = kt << 5;
#pragma unroll
        for (int i = 0; i < 4; i++) {
            const int idx = t + (i << 8);
            const int row = idx >> 3, ch = idx & 7;
            const __nv_bfloat16* px = (ch < 4) ? Xh : Xl;
            const __nv_bfloat16* pw = (ch < 4) ? Wh : Wl;
            const int cc = (ch & 3) << 3;
            const uint32_t so = swz(row, ch);
            CP16(base + so,         px + (size_t)(m0 + row) * D_MODEL + k0 + cc);
            CP16(base + 16384 + so, pw + (size_t)(n0 + row) * D_MODEL + k0 + cc);
        }
    };

    issue(0, 0); CP_COMMIT;
    issue(1, 1); CP_COMMIT;

    for (int kt = 0; kt < 32; kt++) {
        if (kt < 30) { CP_WAIT1; } else { CP_WAIT0; }
        __syncthreads();
        if (kt < 30) { issue(kt + 2, (kt + 2) % 3); CP_COMMIT; }

        const uint32_t abuf = sb + (kt % 3) * GSTG;
        const uint32_t bbuf = abuf + 16384;
#pragma unroll
        for (int ks = 0; ks < 2; ks++) {
            uint32_t bh[4][2], bl[4][2];
#pragma unroll
            for (int p = 0; p < 2; p++) {
                const int nr = wn + (p << 4) + (lane & 7) + ((lane >> 4) << 3);
                const int ch = (ks << 1) + ((lane >> 3) & 1);
                uint32_t qq[4];
                LDM4(qq, bbuf + swz(nr, ch));
                bh[2 * p][0] = qq[0]; bh[2 * p][1] = qq[1];
                bh[2 * p + 1][0] = qq[2]; bh[2 * p + 1][1] = qq[3];
                LDM4(qq, bbuf + swz(nr, ch + 4));
                bl[2 * p][0] = qq[0]; bl[2 * p][1] = qq[1];
                bl[2 * p + 1][0] = qq[2]; bl[2 * p + 1][1] = qq[3];
            }
#pragma unroll
            for (int mi = 0; mi < 4; mi++) {
                const int row = wm + (mi << 4) + (lane & 15);
                const int ch  = (ks << 1) + (lane >> 4);
                uint32_t ah[4], al[4];
                LDM4(ah, abuf + swz(row, ch));
                LDM4(al, abuf + swz(row, ch + 4));
#pragma unroll
                for (int ni = 0; ni < 4; ni++) {
                    MMA_BF16(acc[mi][ni], ah, bh[ni][0], bh[ni][1]);
                    MMA_BF16(acc[mi][ni], ah, bl[ni][0], bl[ni][1]);
                    MMA_BF16(acc[mi][ni], al, bh[ni][0], bh[ni][1]);
                }
            }
        }
    }
}

// ---- batched Q/K/V projections. Q (z==0) pre-scaled by 0.125*log2(e).
//      Q and K stored as SINGLE rn-rounded bf16 planes; V keeps hi/lo. ----
__global__ __launch_bounds__(256, 2) void gemm_qkv_kernel(
    const float* __restrict__ bq, const float* __restrict__ bk,
    const float* __restrict__ bv)
{
    extern __shared__ char sm[];
    const uint32_t sb = smem_u32(sm);
    const int z  = blockIdx.z;
    const int m0 = blockIdx.y << 7;
    const int n0 = blockIdx.x << 7;
    const size_t zo = (size_t)z * NXE;

    float acc[4][4][4] = {};
    gemm_core(g_INh + zo, g_INl + zo,
              g_Wh + (size_t)z * NWE, g_Wl + (size_t)z * NWE,
              sb, m0, n0, acc);

    const float* bias = (z == 0) ? bq : (z == 1) ? bk : bv;
    const float sc = (z == 0) ? (0.125f * LOG2E) : 1.0f;
    __nv_bfloat16* Yh = g_Ph + zo;
    __nv_bfloat16* Yl = g_Pl + zo;

    const int lane = threadIdx.x & 31;
    const int wid  = threadIdx.x >> 5;
    const int wm   = (wid & 1) << 6;
    const int wn   = (wid >> 1) << 5;
    const int lr4  = lane >> 2;
    const int lc2  = (lane & 3) << 1;
#pragma unroll
    for (int mi = 0; mi < 4; mi++) {
        const int r = m0 + wm + (mi << 4) + lr4;
#pragma unroll
        for (int ni = 0; ni < 4; ni++) {
            const int c = n0 + wn + (ni << 3) + lc2;
            const float bx = bias[c], by = bias[c + 1];
            const float v0 = (acc[mi][ni][0] + bx) * sc, v1 = (acc[mi][ni][1] + by) * sc;
            const float v2 = (acc[mi][ni][2] + bx) * sc, v3 = (acc[mi][ni][3] + by) * sc;
            if (z <= 1) {
                // Q, K: single rn plane (symmetric half-ulp residual)
                *(uint32_t*)(Yh + (size_t)r * D_MODEL + c)       = pack_bf16(v0, v1);
                *(uint32_t*)(Yh + (size_t)(r + 8) * D_MODEL + c) = pack_bf16(v2, v3);
            } else {
                *(uint32_t*)(Yh + (size_t)r * D_MODEL + c)       = pack2_hi_trunc(v0, v1);
                *(uint32_t*)(Yl + (size_t)r * D_MODEL + c)       = pack2_lo_trunc(v0, v1);
                *(uint32_t*)(Yh + (size_t)(r + 8) * D_MODEL + c) = pack2_hi_trunc(v2, v3);
                *(uint32_t*)(Yl + (size_t)(r + 8) * D_MODEL + c) = pack2_lo_trunc(v2, v3);
            }
        }
    }
}

// ---- output projection, fp32 epilogue ----
__global__ __launch_bounds__(256, 2) void gemm_out_kernel(
    const float* __restrict__ bo, float* __restrict__ out)
{
    extern __shared__ char sm[];
    const uint32_t sb = smem_u32(sm);
    const int m0 = blockIdx.y << 7;
    const int n0 = blockIdx.x << 7;

    float acc[4][4][4] = {};
    gemm_core(g_Ch, g_Cl, g_Wh + 3 * NWE, g_Wl + 3 * NWE, sb, m0, n0, acc);

    const int lane = threadIdx.x & 31;
    const int wid  = threadIdx.x >> 5;
    const int wm   = (wid & 1) << 6;
    const int wn   = (wid >> 1) << 5;
    const int lr4  = lane >> 2;
    const int lc2  = (lane & 3) << 1;
#pragma unroll
    for (int mi = 0; mi < 4; mi++) {
        const int r = m0 + wm + (mi << 4) + lr4;
#pragma unroll
        for (int ni = 0; ni < 4; ni++) {
            const int c = n0 + wn + (ni << 3) + lc2;
            const float bx = bo[c], by = bo[c + 1];
            float2 o0, o1;
            o0.x = acc[mi][ni][0] + bx; o0.y = acc[mi][ni][1] + by;
            o1.x = acc[mi][ni][2] + bx; o1.y = acc[mi][ni][3] + by;
            *(float2*)(out + (size_t)r * D_MODEL + c)       = o0;
            *(float2*)(out + (size_t)(r + 8) * D_MODEL + c) = o1;
        }
    }
}

// ===========================================================================
// Tensor-core flash attention v9: 256 q-rows per CTA, 8 warps x 32 rows.
// Q AND K are single rn bf16 planes -> QK is ONE MMA per fragment pair:
// attention MMA count 256/tile (was 384 in v7, 320 in v8). K-lo loads and
// ldmatrix gone; stage shrinks to 24K. No-max exp2 softmax; bit-packed
// mask; one __syncthreads per k-tile; P.V keeps full 3-term split.
// smem: Q 32K | 2 x stage(K 8K, Vh 8K, Vl 8K) = 80 KB
// ===========================================================================
#define AS_STG   32768
#define AS_STGSZ 24576
#define AS_VHI   8192
#define AS_VLO   16384
#define ATT_SMEM 81920

__global__ __launch_bounds__(256, 1) void attn_mma_kernel()
{
    extern __shared__ char sm[];
    const uint32_t sb = smem_u32(sm);
    const int t    = threadIdx.x;
    const int lane = t & 31;
    const int w    = t >> 5;
    const int b  = blockIdx.z;
    const int h  = blockIdx.y;
    const int q0 = blockIdx.x << 8;          // 256 q rows per CTA
    const size_t bS   = (size_t)b * SEQ;
    const size_t hoff = (size_t)h * DK;

    const __nv_bfloat16* Qp = g_Ph;
    const __nv_bfloat16* Kp = g_Ph + NXE;
    const __nv_bfloat16* Vh = g_Ph + 2 * NXE;
    const __nv_bfloat16* Vl = g_Pl + 2 * NXE;

    auto issue_stage = [&](int kt, int bufsel) {
        const uint32_t base = sb + AS_STG + bufsel * AS_STGSZ;
#pragma unroll
        for (int i = 0; i < 2; i++) {
            const int idx = t + (i << 8);
            const int row = idx >> 3, ch = idx & 7;
            const size_t go = (bS + (kt << 6) + row) * D_MODEL + hoff + (ch << 3);
            const uint32_t so = swz(row, ch);
            CP16(base + so,          Kp + go);
            CP16(base + AS_VHI + so, Vh + go);
            CP16(base + AS_VLO + so, Vl + go);
        }
    };

    // prologue: Q tile (256 rows, single plane) + stage0; stage1 in group B
#pragma unroll
    for (int i = 0; i < 8; i++) {
        const int idx = t + (i << 8);
        const int row = idx >> 3, ch = idx & 7;
        const size_t go = (bS + q0 + row) * D_MODEL + hoff + (ch << 3);
        CP16(sb + swz(row, ch), Qp + go);
    }
    issue_stage(0, 0);
    CP_COMMIT;
    issue_stage(1, 1);
    CP_COMMIT;
    CP_WAIT1;
    __syncthreads();

    float O[2][8][4] = {};
    float ll[4] = {0.0f, 0.0f, 0.0f, 0.0f};   // per-thread partial row sums

    const int qr0 = q0 + (w << 5) + (lane >> 2);   // warp covers rows qr0..+24
    const int kc  = (lane & 3) << 1;

    for (int kt = 0; kt < SEQ / 64; kt++) {
        const uint32_t kb = sb + AS_STG + (kt & 1) * AS_STGSZ;

        // ---- mask prefetch: 4 u64 words (64 key-bits each) ----
        const uint64_t* Mb = g_maskb + (size_t)qr0 * (SEQ / 64) + kt;
        const uint64_t w0 = Mb[0] >> kc;
        const uint64_t w1 = Mb[(size_t)8  * (SEQ / 64)] >> kc;
        const uint64_t w2 = Mb[(size_t)16 * (SEQ / 64)] >> kc;
        const uint64_t w3 = Mb[(size_t)24 * (SEQ / 64)] >> kc;

        // ---- S = Q . K^T  (single-plane Q and K: 1 MMA per frag pair) ----
        float S[2][8][4] = {};
#pragma unroll
        for (int ks = 0; ks < 4; ks++) {
            uint32_t kh[4][4];
#pragma unroll
            for (int g = 0; g < 4; g++) {
                const int nr = (g << 4) + (lane & 7) + ((lane >> 4) << 3);
                const int ch = (ks << 1) + ((lane >> 3) & 1);
                LDM4(kh[g], kb + swz(nr, ch));
            }
#pragma unroll
            for (int mi = 0; mi < 2; mi++) {
                uint32_t qh[4];
                const int row = (w << 5) + (mi << 4) + (lane & 15);
                const int ch  = (ks << 1) + (lane >> 4);
                LDM4(qh, sb + swz(row, ch));
#pragma unroll
                for (int g = 0; g < 4; g++) {
                    MMA_BF16(S[mi][2 * g],     qh, kh[g][0], kh[g][1]);
                    MMA_BF16(S[mi][2 * g + 1], qh, kh[g][2], kh[g][3]);
                }
            }
        }

        // ---- P = exp2(S); masked -> e^-1; per-thread row-sum partials ----
#pragma unroll
        for (int mi = 0; mi < 2; mi++) {
            const uint64_t wa = mi ? w2 : w0;
            const uint64_t wb = mi ? w3 : w1;
            float rs0 = 0.0f, rs1 = 0.0f;
#pragma unroll
            for (int j = 0; j < 8; j++) {
                const float e0 = ex2f(S[mi][j][0]);
                const float e1 = ex2f(S[mi][j][1]);
                const float e2 = ex2f(S[mi][j][2]);
                const float e3 = ex2f(S[mi][j][3]);
                const uint32_t sa  = (uint32_t)(wa >> (8 * j));
                const uint32_t sbm = (uint32_t)(wb >> (8 * j));
                S[mi][j][0] = (sa  & 1) ? e0 : EXPN1;
                S[mi][j][1] = (sa  & 2) ? e1 : EXPN1;
                S[mi][j][2] = (sbm & 1) ? e2 : EXPN1;
                S[mi][j][3] = (sbm & 2) ? e3 : EXPN1;
                rs0 += S[mi][j][0] + S[mi][j][1];
                rs1 += S[mi][j][2] + S[mi][j][3];
            }
            ll[2 * mi]     += rs0;
            ll[2 * mi + 1] += rs1;
        }

        // ---- O += P . V  (P packed on the fly; full 3-term split) ----
#pragma unroll
        for (int tt = 0; tt < 4; tt++) {
            uint32_t Pha[2][4], Pla[2][4];
#pragma unroll
            for (int mi = 0; mi < 2; mi++) {
                const float* p0 = S[mi][2 * tt];
                const float* p1 = S[mi][2 * tt + 1];
                Pha[mi][0] = pack2_hi_trunc(p0[0], p0[1]);
                Pha[mi][1] = pack2_hi_trunc(p0[2], p0[3]);
                Pha[mi][2] = pack2_hi_trunc(p1[0], p1[1]);
                Pha[mi][3] = pack2_hi_trunc(p1[2], p1[3]);
                Pla[mi][0] = pack2_lo_trunc(p0[0], p0[1]);
                Pla[mi][1] = pack2_lo_trunc(p0[2], p0[3]);
                Pla[mi][2] = pack2_lo_trunc(p1[0], p1[1]);
                Pla[mi][3] = pack2_lo_trunc(p1[2], p1[3]);
            }
#pragma unroll
            for (int g = 0; g < 4; g++) {
                const int row = (tt << 4) + (lane & 15);
                const int ch  = (g << 1) + (lane >> 4);
                const uint32_t va = kb + AS_VHI + swz(row, ch);
                uint32_t vh[4], vl[4];
                LDM4_T(vh, va);
                LDM4_T(vl, va + 8192);
#pragma unroll
                for (int mi = 0; mi < 2; mi++) {
                    MMA_BF16(O[mi][2 * g],     Pha[mi], vh[0], vh[1]);
                    MMA_BF16(O[mi][2 * g],     Pha[mi], vl[0], vl[1]);
                    MMA_BF16(O[mi][2 * g],     Pla[mi], vh[0], vh[1]);
                    MMA_BF16(O[mi][2 * g + 1], Pha[mi], vh[2], vh[3]);
                    MMA_BF16(O[mi][2 * g + 1], Pha[mi], vl[2], vl[3]);
                    MMA_BF16(O[mi][2 * g + 1], Pla[mi], vh[2], vh[3]);
                }
            }
        }

        // ---- pipeline advance: ONE barrier per kt ----
        if (kt < 31) {
            CP_WAIT0;
            __syncthreads();
            if (kt < 30) {
                issue_stage(kt + 2, kt & 1);
                CP_COMMIT;
            }
        }
    }

    // ---- reduce row sums across the 4 lanes per row (once) ----
#pragma unroll
    for (int i = 0; i < 4; i++) {
        ll[i] += __shfl_xor_sync(0xffffffffu, ll[i], 1);
        ll[i] += __shfl_xor_sync(0xffffffffu, ll[i], 2);
    }

    // ---- normalize + write context as bf16 hi/lo planes [B,S,H*DK] ----
#pragma unroll
    for (int mi = 0; mi < 2; mi++) {
        const float i0 = 1.0f / ll[2 * mi];
        const float i1 = 1.0f / ll[2 * mi + 1];
        const size_t co0 = (bS + qr0 + (mi << 4)) * D_MODEL + hoff + kc;
        const size_t co1 = co0 + (size_t)8 * D_MODEL;
#pragma unroll
        for (int j = 0; j < 8; j++) {
            const float v0 = O[mi][j][0] * i0, v1 = O[mi][j][1] * i0;
            const float v2 = O[mi][j][2] * i1, v3 = O[mi][j][3] * i1;
            *(uint32_t*)(g_Ch + co0 + (j << 3)) = pack2_hi_trunc(v0, v1);
            *(uint32_t*)(g_Cl + co0 + (j << 3)) = pack2_lo_trunc(v0, v1);
            *(uint32_t*)(g_Ch + co1 + (j << 3)) = pack2_hi_trunc(v2, v3);
            *(uint32_t*)(g_Cl + co1 + (j << 3)) = pack2_lo_trunc(v2, v3);
        }
    }
}

// ---------------------------------------------------------------------------
extern "C" void kernel_launch(void* const* d_in, const int* in_sizes, int n_in,
                              void* d_out, int out_size)
{
    const float* q    = (const float*)d_in[0];
    const float* k    = (const float*)d_in[1];
    const float* v    = (const float*)d_in[2];
    const int*   mask = (const int*)  d_in[3];
    const float* wq   = (const float*)d_in[4];
    const float* bq   = (const float*)d_in[5];
    const float* wk   = (const float*)d_in[6];
    const float* bk   = (const float*)d_in[7];
    const float* wv   = (const float*)d_in[8];
    const float* bv   = (const float*)d_in[9];
    const float* wo   = (const float*)d_in[10];
    const float* bo   = (const float*)d_in[11];
    float* out = (float*)d_out;

    cudaFuncSetAttribute(gemm_qkv_kernel,
                         cudaFuncAttributeMaxDynamicSharedMemorySize, GEMM_SMEM);
    cudaFuncSetAttribute(gemm_out_kernel,
                         cudaFuncAttributeMaxDynamicSharedMemorySize, GEMM_SMEM);
    cudaFuncSetAttribute(attn_mma_kernel,
                         cudaFuncAttributeMaxDynamicSharedMemorySize, ATT_SMEM);

    // merged prepass: 3*4096 input + 4*1024 weight + 512 mask blocks
    split_all_kernel<<<16896, 256>>>(q, k, v, wq, wk, wv, wo, mask);

    gemm_qkv_kernel<<<dim3(8, 32, 3), 256, GEMM_SMEM>>>(bq, bk, bv);

    attn_mma_kernel<<<dim3(SEQ / 256, NHEAD, BATCH), 256, ATT_SMEM>>>();

    gemm_out_kernel<<<dim3(8, 32, 1), 256, GEMM_SMEM>>>(bo, out);
}

// round 16
// speedup vs baseline: 1.3433x; 1.1761x over previous
#include <cuda_runtime.h>
#include <cuda_bf16.h>
#include <cstdint>
#include <cstddef>

#define D_MODEL 1024
#define NHEAD   16
#define DK      64
#define BATCH   2
#define SEQ     2048
#define M_TOT   (BATCH * SEQ)                 // 4096
#define NXE     ((size_t)M_TOT * D_MODEL)     // 4M elems
#define NWE     ((size_t)D_MODEL * D_MODEL)   // 1M elems
#define LOG2E   1.4426950408889634f
#define EXPN1   0.36787944117144233f          // e^-1 (masked-score weight)

// Scratch (allocation-free: __device__ globals)
__device__ __nv_bfloat16 g_INh[3 * NXE];   // q,k: rn plane; v: trunc hi
__device__ __nv_bfloat16 g_INl[3 * NXE];   // v lo (q,k regions unused)
__device__ __nv_bfloat16 g_Wh[4 * NWE];    // wq,wk: rn; wv,wo: trunc hi
__device__ __nv_bfloat16 g_Wl[4 * NWE];    // wv,wo lo
__device__ __nv_bfloat16 g_Ph[3 * NXE];    // projected Q,K (rn bf16), V (hi)
__device__ __nv_bfloat16 g_Pl[3 * NXE];    // (lo; Q,K regions unused)
__device__ __nv_bfloat16 g_Ch[NXE];        // attention context (hi)
__device__ __nv_bfloat16 g_Cl[NXE];        // (lo)
__device__ uint64_t      g_maskb[(size_t)SEQ * SEQ / 64];  // bit-packed mask

// ===========================================================================
// Helpers (baseline PTX ISA only — compute_103-safe)
// ===========================================================================
__device__ __forceinline__ uint32_t smem_u32(const void* p) {
    uint32_t a;
    asm("{ .reg .u64 t; cvta.to.shared.u64 t, %1; cvt.u32.u64 %0, t; }"
        : "=r"(a) : "l"(p));
    return a;
}

__device__ __forceinline__ float ex2f(float x) {
    float y;
    asm("ex2.approx.f32 %0, %1;" : "=f"(y) : "f"(x));
    return y;
}

#define LDM4(r, addr) \
    asm volatile("ldmatrix.sync.aligned.m8n8.x4.shared.b16 {%0,%1,%2,%3}, [%4];" \
        : "=r"((r)[0]), "=r"((r)[1]), "=r"((r)[2]), "=r"((r)[3]) : "r"(addr))

#define LDM4_T(r, addr) \
    asm volatile("ldmatrix.sync.aligned.m8n8.x4.trans.shared.b16 {%0,%1,%2,%3}, [%4];" \
        : "=r"((r)[0]), "=r"((r)[1]), "=r"((r)[2]), "=r"((r)[3]) : "r"(addr))

#define MMA_BF16(d, a, b0, b1) \
    asm volatile("mma.sync.aligned.m16n8k16.row.col.f32.bf16.bf16.f32 " \
        "{%0,%1,%2,%3}, {%4,%5,%6,%7}, {%8,%9}, {%0,%1,%2,%3};" \
        : "+f"((d)[0]), "+f"((d)[1]), "+f"((d)[2]), "+f"((d)[3]) \
        : "r"((a)[0]), "r"((a)[1]), "r"((a)[2]), "r"((a)[3]), "r"(b0), "r"(b1))

#define CP16(sa, gp) \
    asm volatile("{ .reg .u64 g; cvta.to.global.u64 g, %1; " \
                 "cp.async.cg.shared.global [%0], [g], 16; }" \
        :: "r"((uint32_t)(sa)), "l"(gp) : "memory")
#define CP_COMMIT  asm volatile("cp.async.commit_group;" ::: "memory")
#define CP_WAIT1   asm volatile("cp.async.wait_group 1;" ::: "memory")
#define CP_WAIT0   asm volatile("cp.async.wait_group 0;" ::: "memory")

__device__ __forceinline__ uint32_t pack_bf16(float a, float b) {
    __nv_bfloat162 h = __floats2bfloat162_rn(a, b);
    return *(uint32_t*)&h;
}
// Truncation split: hi = top 16 bits of fp32, lo = exact residual rounded.
__device__ __forceinline__ uint32_t pack2_hi_trunc(float a, float b) {
    return __byte_perm(__float_as_uint(a), __float_as_uint(b), 0x7632);
}
__device__ __forceinline__ uint32_t pack2_lo_trunc(float a, float b) {
    float ah = __uint_as_float(__float_as_uint(a) & 0xFFFF0000u);
    float bh = __uint_as_float(__float_as_uint(b) & 0xFFFF0000u);
    return pack_bf16(a - ah, b - bh);
}
__device__ __forceinline__ void cvt4_split(float4 f, uint2& hi, uint2& lo) {
    hi.x = pack2_hi_trunc(f.x, f.y);  hi.y = pack2_hi_trunc(f.z, f.w);
    lo.x = pack2_lo_trunc(f.x, f.y);  lo.y = pack2_lo_trunc(f.z, f.w);
}

// XOR swizzle: 128B rows, 16B chunks permuted within row (ldmatrix-safe)
__device__ __forceinline__ uint32_t swz(uint32_t row, uint32_t chunk) {
    return (row << 7) + ((chunk ^ (row & 7)) << 4);
}

// ===========================================================================
// Merged pre-pass. q,k inputs and wq,wk weights -> single rn bf16 plane;
// v input and wv,wo -> trunc hi/lo planes; mask -> bit-pack.
// ===========================================================================
__global__ void split_all_kernel(
    const float* __restrict__ q,  const float* __restrict__ k,
    const float* __restrict__ v,
    const float* __restrict__ w0, const float* __restrict__ w1,
    const float* __restrict__ w2, const float* __restrict__ w3,
    const int*   __restrict__ m)
{
    const int blk = blockIdx.x;
    if (blk >= 16384) {                      // mask bit-pack: 512 blocks
        const size_t tid  = (size_t)(blk - 16384) * 256 + threadIdx.x;
        const size_t base = tid << 5;        // 32 consecutive ints
        uint32_t bits = 0;
#pragma unroll
        for (int i = 0; i < 8; i++) {
            int4 vv = *(const int4*)(m + base + (i << 2));
            bits |= (vv.x ? 1u : 0u) << (4 * i);
            bits |= (vv.y ? 1u : 0u) << (4 * i + 1);
            bits |= (vv.z ? 1u : 0u) << (4 * i + 2);
            bits |= (vv.w ? 1u : 0u) << (4 * i + 3);
        }
        ((uint32_t*)g_maskb)[tid] = bits;
        return;
    }
    const float* src;
    __nv_bfloat16 *dh, *dl;
    size_t i;
    bool rn_only;
    if (blk < 12288) {                       // inputs: 3 x 4096 blocks
        const int z = blk >> 12;
        src = (z == 0) ? q : (z == 1) ? k : v;
        i = ((size_t)(blk & 4095) * 256 + threadIdx.x) << 2;
        dh = g_INh + (size_t)z * NXE;
        dl = g_INl + (size_t)z * NXE;
        rn_only = (z <= 1);
    } else {                                 // weights: 4 x 1024 blocks
        const int wblk = blk - 12288;
        const int z = wblk >> 10;
        src = (z == 0) ? w0 : (z == 1) ? w1 : (z == 2) ? w2 : w3;
        i = ((size_t)(wblk & 1023) * 256 + threadIdx.x) << 2;
        dh = g_Wh + (size_t)z * NWE;
        dl = g_Wl + (size_t)z * NWE;
        rn_only = (z <= 1);
    }
    float4 f = *(const float4*)(src + i);
    if (rn_only) {
        uint2 hi;
        hi.x = pack_bf16(f.x, f.y);
        hi.y = pack_bf16(f.z, f.w);
        *(uint2*)(dh + i) = hi;
    } else {
        uint2 hi, lo; cvt4_split(f, hi, lo);
        *(uint2*)(dh + i) = hi;
        *(uint2*)(dl + i) = lo;
    }
}

// ===========================================================================
// Lean single-plane bf16 GEMM for Q/K projections.
// CTA tile 128x128, BK=64, 3-stage pipeline (stage 32K: A 16K + B 16K).
// 1 MMA per fragment pair (plain bf16 GEMM). Epilogue: rn bf16 plane;
// Q (z==0) pre-scaled by 0.125*log2(e).
// ===========================================================================
#define QK_STG  32768
#define QK_SMEM (3 * QK_STG)   // 98304

__global__ __launch_bounds__(256, 2) void gemm_qk_kernel(
    const float* __restrict__ bq, const float* __restrict__ bk)
{
    extern __shared__ char sm[];
    const uint32_t sb = smem_u32(sm);
    const int t    = threadIdx.x;
    const int lane = t & 31;
    const int wid  = t >> 5;
    const int wm   = (wid & 1) << 6;
    const int wn   = (wid >> 1) << 5;
    const int z  = blockIdx.z;               // 0=Q, 1=K
    const int m0 = blockIdx.y << 7;
    const int n0 = blockIdx.x << 7;
    const __nv_bfloat16* Xp = g_INh + (size_t)z * NXE;
    const __nv_bfloat16* Wp = g_Wh + (size_t)z * NWE;

    auto issue = [&](int kt, int s) {
        const uint32_t base = sb + s * QK_STG;
        const int k0 = kt << 6;
#pragma unroll
        for (int i = 0; i < 4; i++) {
            const int idx = t + (i << 8);
            const int row = idx >> 3, ch = idx & 7;
            const int cc = ch << 3;
            const uint32_t so = swz(row, ch);
            CP16(base + so,         Xp + (size_t)(m0 + row) * D_MODEL + k0 + cc);
            CP16(base + 16384 + so, Wp + (size_t)(n0 + row) * D_MODEL + k0 + cc);
        }
    };

    issue(0, 0); CP_COMMIT;
    issue(1, 1); CP_COMMIT;

    float acc[4][4][4] = {};

    for (int kt = 0; kt < 16; kt++) {         // BK=64, 16 k-tiles
        if (kt < 14) { CP_WAIT1; } else { CP_WAIT0; }
        __syncthreads();
        if (kt < 14) { issue(kt + 2, (kt + 2) % 3); CP_COMMIT; }

        const uint32_t abuf = sb + (kt % 3) * QK_STG;
        const uint32_t bbuf = abuf + 16384;
#pragma unroll
        for (int ks = 0; ks < 4; ks++) {
            uint32_t bh[4][2];
#pragma unroll
            for (int p = 0; p < 2; p++) {
                const int nr = wn + (p << 4) + (lane & 7) + ((lane >> 4) << 3);
                const int ch = (ks << 1) + ((lane >> 3) & 1);
                uint32_t qq[4];
                LDM4(qq, bbuf + swz(nr, ch));
                bh[2 * p][0] = qq[0]; bh[2 * p][1] = qq[1];
                bh[2 * p + 1][0] = qq[2]; bh[2 * p + 1][1] = qq[3];
            }
#pragma unroll
            for (int mi = 0; mi < 4; mi++) {
                const int row = wm + (mi << 4) + (lane & 15);
                const int ch  = (ks << 1) + (lane >> 4);
                uint32_t ah[4];
                LDM4(ah, abuf + swz(row, ch));
#pragma unroll
                for (int ni = 0; ni < 4; ni++)
                    MMA_BF16(acc[mi][ni], ah, bh[ni][0], bh[ni][1]);
            }
        }
    }

    const float* bias = z ? bk : bq;
    const float sc = z ? 1.0f : (0.125f * LOG2E);
    __nv_bfloat16* Yh = g_Ph + (size_t)z * NXE;
    const int lr4 = lane >> 2;
    const int lc2 = (lane & 3) << 1;
#pragma unroll
    for (int mi = 0; mi < 4; mi++) {
        const int r = m0 + wm + (mi << 4) + lr4;
#pragma unroll
        for (int ni = 0; ni < 4; ni++) {
            const int c = n0 + wn + (ni << 3) + lc2;
            const float bx = bias[c], by = bias[c + 1];
            const float v0 = (acc[mi][ni][0] + bx) * sc, v1 = (acc[mi][ni][1] + by) * sc;
            const float v2 = (acc[mi][ni][2] + bx) * sc, v3 = (acc[mi][ni][3] + by) * sc;
            *(uint32_t*)(Yh + (size_t)r * D_MODEL + c)       = pack_bf16(v0, v1);
            *(uint32_t*)(Yh + (size_t)(r + 8) * D_MODEL + c) = pack_bf16(v2, v3);
        }
    }
}

// ===========================================================================
// 3-term split GEMM core (trunc hi/lo operands, cp.async 3-stage pipeline)
// CTA tile 128x128, BK=32. Used by the V projection and output projection.
// ===========================================================================
#define GSTG      32768
#define GEMM_SMEM (3 * GSTG)   // 98304

__device__ __forceinline__ void gemm_core(
    const __nv_bfloat16* __restrict__ Xh, const __nv_bfloat16* __restrict__ Xl,
    const __nv_bfloat16* __restrict__ Wh, const __nv_bfloat16* __restrict__ Wl,
    uint32_t sb, int m0, int n0, float (&acc)[4][4][4])
{
    const int t    = threadIdx.x;
    const int lane = t & 31;
    const int wid  = t >> 5;
    const int wm   = (wid & 1) << 6;
    const int wn   = (wid >> 1) << 5;

    auto issue = [&](int kt, int s) {
        const uint32_t base = sb + s * GSTG;
        const int k0 = kt << 5;
#pragma unroll
        for (int i = 0; i < 4; i++) {
            const int idx = t + (i << 8);
            const int row = idx >> 3, ch = idx & 7;
            const __nv_bfloat16* px = (ch < 4) ? Xh : Xl;
            const __nv_bfloat16* pw = (ch < 4) ? Wh : Wl;
            const int cc = (ch & 3) << 3;
            const uint32_t so = swz(row, ch);
            CP16(base + so,         px + (size_t)(m0 + row) * D_MODEL + k0 + cc);
            CP16(base + 16384 + so, pw + (size_t)(n0 + row) * D_MODEL + k0 + cc);
        }
    };

    issue(0, 0); CP_COMMIT;
    issue(1, 1); CP_COMMIT;

    for (int kt = 0; kt < 32; kt++) {
        if (kt < 30) { CP_WAIT1; } else { CP_WAIT0; }
        __syncthreads();
        if (kt < 30) { issue(kt + 2, (kt + 2) % 3); CP_COMMIT; }

        const uint32_t abuf = sb + (kt % 3) * GSTG;
        const uint32_t bbuf = abuf + 16384;
#pragma unroll
        for (int ks = 0; ks < 2; ks++) {
            uint32_t bh[4][2], bl[4][2];
#pragma unroll
            for (int p = 0; p < 2; p++) {
                const int nr = wn + (p << 4) + (lane & 7) + ((lane >> 4) << 3);
                const int ch = (ks << 1) + ((lane >> 3) & 1);
                uint32_t qq[4];
                LDM4(qq, bbuf + swz(nr, ch));
                bh[2 * p][0] = qq[0]; bh[2 * p][1] = qq[1];
                bh[2 * p + 1][0] = qq[2]; bh[2 * p + 1][1] = qq[3];
                LDM4(qq, bbuf + swz(nr, ch + 4));
                bl[2 * p][0] = qq[0]; bl[2 * p][1] = qq[1];
                bl[2 * p + 1][0] = qq[2]; bl[2 * p + 1][1] = qq[3];
            }
#pragma unroll
            for (int mi = 0; mi < 4; mi++) {
                const int row = wm + (mi << 4) + (lane & 15);
                const int ch  = (ks << 1) + (lane >> 4);
                uint32_t ah[4], al[4];
                LDM4(ah, abuf + swz(row, ch));
                LDM4(al, abuf + swz(row, ch + 4));
#pragma unroll
                for (int ni = 0; ni < 4; ni++) {
                    MMA_BF16(acc[mi][ni], ah, bh[ni][0], bh[ni][1]);
                    MMA_BF16(acc[mi][ni], ah, bl[ni][0], bl[ni][1]);
                    MMA_BF16(acc[mi][ni], al, bh[ni][0], bh[ni][1]);
                }
            }
        }
    }
}

// ---- V projection (3-term, hi/lo epilogue) ----
__global__ __launch_bounds__(256, 2) void gemm_v_kernel(const float* __restrict__ bv)
{
    extern __shared__ char sm[];
    const uint32_t sb = smem_u32(sm);
    const int m0 = blockIdx.y << 7;
    const int n0 = blockIdx.x << 7;

    float acc[4][4][4] = {};
    gemm_core(g_INh + 2 * NXE, g_INl + 2 * NXE,
              g_Wh + 2 * NWE, g_Wl + 2 * NWE, sb, m0, n0, acc);

    __nv_bfloat16* Yh = g_Ph + 2 * NXE;
    __nv_bfloat16* Yl = g_Pl + 2 * NXE;
    const int lane = threadIdx.x & 31;
    const int wid  = threadIdx.x >> 5;
    const int wm   = (wid & 1) << 6;
    const int wn   = (wid >> 1) << 5;
    const int lr4  = lane >> 2;
    const int lc2  = (lane & 3) << 1;
#pragma unroll
    for (int mi = 0; mi < 4; mi++) {
        const int r = m0 + wm + (mi << 4) + lr4;
#pragma unroll
        for (int ni = 0; ni < 4; ni++) {
            const int c = n0 + wn + (ni << 3) + lc2;
            const float bx = bv[c], by = bv[c + 1];
            const float v0 = acc[mi][ni][0] + bx, v1 = acc[mi][ni][1] + by;
            const float v2 = acc[mi][ni][2] + bx, v3 = acc[mi][ni][3] + by;
            *(uint32_t*)(Yh + (size_t)r * D_MODEL + c)       = pack2_hi_trunc(v0, v1);
            *(uint32_t*)(Yl + (size_t)r * D_MODEL + c)       = pack2_lo_trunc(v0, v1);
            *(uint32_t*)(Yh + (size_t)(r + 8) * D_MODEL + c) = pack2_hi_trunc(v2, v3);
            *(uint32_t*)(Yl + (size_t)(r + 8) * D_MODEL + c) = pack2_lo_trunc(v2, v3);
        }
    }
}

// ---- output projection, fp32 epilogue ----
__global__ __launch_bounds__(256, 2) void gemm_out_kernel(
    const float* __restrict__ bo, float* __restrict__ out)
{
    extern __shared__ char sm[];
    const uint32_t sb = smem_u32(sm);
    const int m0 = blockIdx.y << 7;
    const int n0 = blockIdx.x << 7;

    float acc[4][4][4] = {};
    gemm_core(g_Ch, g_Cl, g_Wh + 3 * NWE, g_Wl + 3 * NWE, sb, m0, n0, acc);

    const int lane = threadIdx.x & 31;
    const int wid  = threadIdx.x >> 5;
    const int wm   = (wid & 1) << 6;
    const int wn   = (wid >> 1) << 5;
    const int lr4  = lane >> 2;
    const int lc2  = (lane & 3) << 1;
#pragma unroll
    for (int mi = 0; mi < 4; mi++) {
        const int r = m0 + wm + (mi << 4) + lr4;
#pragma unroll
        for (int ni = 0; ni < 4; ni++) {
            const int c = n0 + wn + (ni << 3) + lc2;
            const float bx = bo[c], by = bo[c + 1];
            float2 o0, o1;
            o0.x = acc[mi][ni][0] + bx; o0.y = acc[mi][ni][1] + by;
            o1.x = acc[mi][ni][2] + bx; o1.y = acc[mi][ni][3] + by;
            *(float2*)(out + (size_t)r * D_MODEL + c)       = o0;
            *(float2*)(out + (size_t)(r + 8) * D_MODEL + c) = o1;
        }
    }
}

// ===========================================================================
// Tensor-core flash attention v9 (unchanged from round 15): 256 q-rows/CTA,
// single-plane Q,K (1 MMA per QK frag pair); V/P keep 3-term split.
// smem: Q 32K | 2 x stage(K 8K, Vh 8K, Vl 8K) = 80 KB
// ===========================================================================
#define AS_STG   32768
#define AS_STGSZ 24576
#define AS_VHI   8192
#define AS_VLO   16384
#define ATT_SMEM 81920

__global__ __launch_bounds__(256, 1) void attn_mma_kernel()
{
    extern __shared__ char sm[];
    const uint32_t sb = smem_u32(sm);
    const int t    = threadIdx.x;
    const int lane = t & 31;
    const int w    = t >> 5;
    const int b  = blockIdx.z;
    const int h  = blockIdx.y;
    const int q0 = blockIdx.x << 8;          // 256 q rows per CTA
    const size_t bS   = (size_t)b * SEQ;
    const size_t hoff = (size_t)h * DK;

    const __nv_bfloat16* Qp = g_Ph;
    const __nv_bfloat16* Kp = g_Ph + NXE;
    const __nv_bfloat16* Vh = g_Ph + 2 * NXE;
    const __nv_bfloat16* Vl = g_Pl + 2 * NXE;

    auto issue_stage = [&](int kt, int bufsel) {
        const uint32_t base = sb + AS_STG + bufsel * AS_STGSZ;
#pragma unroll
        for (int i = 0; i < 2; i++) {
            const int idx = t + (i << 8);
            const int row = idx >> 3, ch = idx & 7;
            const size_t go = (bS + (kt << 6) + row) * D_MODEL + hoff + (ch << 3);
            const uint32_t so = swz(row, ch);
            CP16(base + so,          Kp + go);
            CP16(base + AS_VHI + so, Vh + go);
            CP16(base + AS_VLO + so, Vl + go);
        }
    };

#pragma unroll
    for (int i = 0; i < 8; i++) {
        const int idx = t + (i << 8);
        const int row = idx >> 3, ch = idx & 7;
        const size_t go = (bS + q0 + row) * D_MODEL + hoff + (ch << 3);
        CP16(sb + swz(row, ch), Qp + go);
    }
    issue_stage(0, 0);
    CP_COMMIT;
    issue_stage(1, 1);
    CP_COMMIT;
    CP_WAIT1;
    __syncthreads();

    float O[2][8][4] = {};
    float ll[4] = {0.0f, 0.0f, 0.0f, 0.0f};

    const int qr0 = q0 + (w << 5) + (lane >> 2);
    const int kc  = (lane & 3) << 1;

    for (int kt = 0; kt < SEQ / 64; kt++) {
        const uint32_t kb = sb + AS_STG + (kt & 1) * AS_STGSZ;

        const uint64_t* Mb = g_maskb + (size_t)qr0 * (SEQ / 64) + kt;
        const uint64_t w0 = Mb[0] >> kc;
        const uint64_t w1 = Mb[(size_t)8  * (SEQ / 64)] >> kc;
        const uint64_t w2 = Mb[(size_t)16 * (SEQ / 64)] >> kc;
        const uint64_t w3 = Mb[(size_t)24 * (SEQ / 64)] >> kc;

        float S[2][8][4] = {};
#pragma unroll
        for (int ks = 0; ks < 4; ks++) {
            uint32_t kh[4][4];
#pragma unroll
            for (int g = 0; g < 4; g++) {
                const int nr = (g << 4) + (lane & 7) + ((lane >> 4) << 3);
                const int ch = (ks << 1) + ((lane >> 3) & 1);
                LDM4(kh[g], kb + swz(nr, ch));
            }
#pragma unroll
            for (int mi = 0; mi < 2; mi++) {
                uint32_t qh[4];
                const int row = (w << 5) + (mi << 4) + (lane & 15);
                const int ch  = (ks << 1) + (lane >> 4);
                LDM4(qh, sb + swz(row, ch));
#pragma unroll
                for (int g = 0; g < 4; g++) {
                    MMA_BF16(S[mi][2 * g],     qh, kh[g][0], kh[g][1]);
                    MMA_BF16(S[mi][2 * g + 1], qh, kh[g][2], kh[g][3]);
                }
            }
        }

#pragma unroll
        for (int mi = 0; mi < 2; mi++) {
            const uint64_t wa = mi ? w2 : w0;
            const uint64_t wb = mi ? w3 : w1;
            float rs0 = 0.0f, rs1 = 0.0f;
#pragma unroll
            for (int j = 0; j < 8; j++) {
                const float e0 = ex2f(S[mi][j][0]);
                const float e1 = ex2f(S[mi][j][1]);
                const float e2 = ex2f(S[mi][j][2]);
                const float e3 = ex2f(S[mi][j][3]);
                const uint32_t sa  = (uint32_t)(wa >> (8 * j));
                const uint32_t sbm = (uint32_t)(wb >> (8 * j));
                S[mi][j][0] = (sa  & 1) ? e0 : EXPN1;
                S[mi][j][1] = (sa  & 2) ? e1 : EXPN1;
                S[mi][j][2] = (sbm & 1) ? e2 : EXPN1;
                S[mi][j][3] = (sbm & 2) ? e3 : EXPN1;
                rs0 += S[mi][j][0] + S[mi][j][1];
                rs1 += S[mi][j][2] + S[mi][j][3];
            }
            ll[2 * mi]     += rs0;
            ll[2 * mi + 1] += rs1;
        }

#pragma unroll
        for (int tt = 0; tt < 4; tt++) {
            uint32_t Pha[2][4], Pla[2][4];
#pragma unroll
            for (int mi = 0; mi < 2; mi++) {
                const float* p0 = S[mi][2 * tt];
                const float* p1 = S[mi][2 * tt + 1];
                Pha[mi][0] = pack2_hi_trunc(p0[0], p0[1]);
                Pha[mi][1] = pack2_hi_trunc(p0[2], p0[3]);
                Pha[mi][2] = pack2_hi_trunc(p1[0], p1[1]);
                Pha[mi][3] = pack2_hi_trunc(p1[2], p1[3]);
                Pla[mi][0] = pack2_lo_trunc(p0[0], p0[1]);
                Pla[mi][1] = pack2_lo_trunc(p0[2], p0[3]);
                Pla[mi][2] = pack2_lo_trunc(p1[0], p1[1]);
                Pla[mi][3] = pack2_lo_trunc(p1[2], p1[3]);
            }
#pragma unroll
            for (int g = 0; g < 4; g++) {
                const int row = (tt << 4) + (lane & 15);
                const int ch  = (g << 1) + (lane >> 4);
                const uint32_t va = kb + AS_VHI + swz(row, ch);
                uint32_t vh[4], vl[4];
                LDM4_T(vh, va);
                LDM4_T(vl, va + 8192);
#pragma unroll
                for (int mi = 0; mi < 2; mi++) {
                    MMA_BF16(O[mi][2 * g],     Pha[mi], vh[0], vh[1]);
                    MMA_BF16(O[mi][2 * g],     Pha[mi], vl[0], vl[1]);
                    MMA_BF16(O[mi][2 * g],     Pla[mi], vh[0], vh[1]);
                    MMA_BF16(O[mi][2 * g + 1], Pha[mi], vh[2], vh[3]);
                    MMA_BF16(O[mi][2 * g + 1], Pha[mi], vl[2], vl[3]);
                    MMA_BF16(O[mi][2 * g + 1], Pla[mi], vh[2], vh[3]);
                }
            }
        }

        if (kt < 31) {
            CP_WAIT0;
            __syncthreads();
            if (kt < 30) {
                issue_stage(kt + 2, kt & 1);
                CP_COMMIT;
            }
        }
    }

#pragma unroll
    for (int i = 0; i < 4; i++) {
        ll[i] += __shfl_xor_sync(0xffffffffu, ll[i], 1);
        ll[i] += __shfl_xor_sync(0xffffffffu, ll[i], 2);
    }

#pragma unroll
    for (int mi = 0; mi < 2; mi++) {
        const float i0 = 1.0f / ll[2 * mi];
        const float i1 = 1.0f / ll[2 * mi + 1];
        const size_t co0 = (bS + qr0 + (mi << 4)) * D_MODEL + hoff + kc;
        const size_t co1 = co0 + (size_t)8 * D_MODEL;
#pragma unroll
        for (int j = 0; j < 8; j++) {
            const float v0 = O[mi][j][0] * i0, v1 = O[mi][j][1] * i0;
            const float v2 = O[mi][j][2] * i1, v3 = O[mi][j][3] * i1;
            *(uint32_t*)(g_Ch + co0 + (j << 3)) = pack2_hi_trunc(v0, v1);
            *(uint32_t*)(g_Cl + co0 + (j << 3)) = pack2_lo_trunc(v0, v1);
            *(uint32_t*)(g_Ch + co1 + (j << 3)) = pack2_hi_trunc(v2, v3);
            *(uint32_t*)(g_Cl + co1 + (j << 3)) = pack2_lo_trunc(v2, v3);
        }
    }
}

// ---------------------------------------------------------------------------
extern "C" void kernel_launch(void* const* d_in, const int* in_sizes, int n_in,
                              void* d_out, int out_size)
{
    const float* q    = (const float*)d_in[0];
    const float* k    = (const float*)d_in[1];
    const float* v    = (const float*)d_in[2];
    const int*   mask = (const int*)  d_in[3];
    const float* wq   = (const float*)d_in[4];
    const float* bq   = (const float*)d_in[5];
    const float* wk   = (const float*)d_in[6];
    const float* bk   = (const float*)d_in[7];
    const float* wv   = (const float*)d_in[8];
    const float* bv   = (const float*)d_in[9];
    const float* wo   = (const float*)d_in[10];
    const float* bo   = (const float*)d_in[11];
    float* out = (float*)d_out;

    cudaFuncSetAttribute(gemm_qk_kernel,
                         cudaFuncAttributeMaxDynamicSharedMemorySize, QK_SMEM);
    cudaFuncSetAttribute(gemm_v_kernel,
                         cudaFuncAttributeMaxDynamicSharedMemorySize, GEMM_SMEM);
    cudaFuncSetAttribute(gemm_out_kernel,
                         cudaFuncAttributeMaxDynamicSharedMemorySize, GEMM_SMEM);
    cudaFuncSetAttribute(attn_mma_kernel,
                         cudaFuncAttributeMaxDynamicSharedMemorySize, ATT_SMEM);

    // merged prepass: 3*4096 input + 4*1024 weight + 512 mask blocks
    split_all_kernel<<<16896, 256>>>(q, k, v, wq, wk, wv, wo, mask);

    gemm_v_kernel<<<dim3(8, 32, 1), 256, GEMM_SMEM>>>(bv);
    gemm_qk_kernel<<<dim3(8, 32, 2), 256, QK_SMEM>>>(bq, bk);

    attn_mma_kernel<<<dim3(SEQ / 256, NHEAD, BATCH), 256, ATT_SMEM>>>();

    gemm_out_kernel<<<dim3(8, 32, 1), 256, GEMM_SMEM>>>(bo, out);
}